// round 1
// baseline (speedup 1.0000x reference)
#include <cuda_runtime.h>
#include <cstddef>

// Problem constants
#define BB 4
#define SS 2048
#define DD 1024

// Scratch (allocation-free rule: __device__ globals)
__device__ float g_Q[BB * SS * DD];
__device__ float g_K[BB * SS * DD];
__device__ float g_V[BB * SS * DD];
__device__ float g_P[(size_t)BB * SS * SS];   // scores -> probabilities (64 MB)

// ---------------------------------------------------------------------------
// GEMM NT: C[m,n] = sum_k A[m,k] * B[n,k]   (A: [M,K] row-major, B: [N,K] row-major)
// 128x128 block tile, TK=8, 256 threads, 8x8 per thread (split-quadrant frags).
// lda == ldb == K.  Batched via blockIdx.z with element strides sA/sB/sC.
// CAUSAL: skip blocks strictly above the diagonal (bx > by).
// ---------------------------------------------------------------------------
template<bool CAUSAL>
__global__ void __launch_bounds__(256) gemm_nt_kernel(
    const float* __restrict__ Ab, const float* __restrict__ Bb, float* __restrict__ Cb,
    int K, int ldc, size_t sA, size_t sB, size_t sC)
{
    int bx = blockIdx.x, by = blockIdx.y;
    if (CAUSAL && bx > by) return;

    const float* A = Ab + blockIdx.z * sA + (size_t)by * 128 * K;
    const float* B = Bb + blockIdx.z * sB + (size_t)bx * 128 * K;
    float*       C = Cb + blockIdx.z * sC + (size_t)by * 128 * ldc + bx * 128;

    __shared__ float As[8][128];
    __shared__ float Bs[8][128];

    int tid  = threadIdx.x;
    int tx   = tid & 15;        // 0..15 -> output cols
    int ty   = tid >> 4;        // 0..15 -> output rows
    int lrow = tid >> 1;        // 0..127 load row
    int lcol = (tid & 1) * 4;   // 0 or 4 (k offset)

    float acc[8][8];
    #pragma unroll
    for (int i = 0; i < 8; i++)
        #pragma unroll
        for (int j = 0; j < 8; j++) acc[i][j] = 0.f;

    for (int k0 = 0; k0 < K; k0 += 8) {
        float4 av = *(const float4*)(A + (size_t)lrow * K + k0 + lcol);
        float4 bv = *(const float4*)(B + (size_t)lrow * K + k0 + lcol);
        As[lcol + 0][lrow] = av.x; As[lcol + 1][lrow] = av.y;
        As[lcol + 2][lrow] = av.z; As[lcol + 3][lrow] = av.w;
        Bs[lcol + 0][lrow] = bv.x; Bs[lcol + 1][lrow] = bv.y;
        Bs[lcol + 2][lrow] = bv.z; Bs[lcol + 3][lrow] = bv.w;
        __syncthreads();

        #pragma unroll
        for (int kk = 0; kk < 8; kk++) {
            float a[8], b[8];
            *(float4*)(a)     = *(const float4*)&As[kk][ty * 4];
            *(float4*)(a + 4) = *(const float4*)&As[kk][64 + ty * 4];
            *(float4*)(b)     = *(const float4*)&Bs[kk][tx * 4];
            *(float4*)(b + 4) = *(const float4*)&Bs[kk][64 + tx * 4];
            #pragma unroll
            for (int i = 0; i < 8; i++)
                #pragma unroll
                for (int j = 0; j < 8; j++)
                    acc[i][j] += a[i] * b[j];
        }
        __syncthreads();
    }

    #pragma unroll
    for (int i = 0; i < 8; i++) {
        int row = (i < 4) ? (ty * 4 + i) : (64 + ty * 4 + (i - 4));
        float* cr = C + (size_t)row * ldc;
        *(float4*)(cr + tx * 4)      = make_float4(acc[i][0], acc[i][1], acc[i][2], acc[i][3]);
        *(float4*)(cr + 64 + tx * 4) = make_float4(acc[i][4], acc[i][5], acc[i][6], acc[i][7]);
    }
}

// ---------------------------------------------------------------------------
// GEMM NN: C[m,n] = sum_k A[m,k] * B[k,n]
// CAUSAL_K: truncate k-loop to (by+1)*128 (P is lower-triangular).
// ---------------------------------------------------------------------------
template<bool CAUSAL_K>
__global__ void __launch_bounds__(256) gemm_nn_kernel(
    const float* __restrict__ Ab, const float* __restrict__ Bb, float* __restrict__ Cb,
    int K, int lda, int ldb, int ldc, size_t sA, size_t sB, size_t sC)
{
    int bx = blockIdx.x, by = blockIdx.y;

    const float* A = Ab + blockIdx.z * sA + (size_t)by * 128 * lda;
    const float* B = Bb + blockIdx.z * sB + bx * 128;
    float*       C = Cb + blockIdx.z * sC + (size_t)by * 128 * ldc + bx * 128;

    __shared__ float As[8][128];
    __shared__ float Bs[8][128];

    int tid  = threadIdx.x;
    int tx   = tid & 15;
    int ty   = tid >> 4;
    int lrow = tid >> 1;
    int lcol = (tid & 1) * 4;
    int brow = tid >> 5;        // 0..7   (k within tile)
    int bcol = (tid & 31) * 4;  // 0..124 (n within tile)

    int kend = CAUSAL_K ? min(K, (by + 1) * 128) : K;

    float acc[8][8];
    #pragma unroll
    for (int i = 0; i < 8; i++)
        #pragma unroll
        for (int j = 0; j < 8; j++) acc[i][j] = 0.f;

    for (int k0 = 0; k0 < kend; k0 += 8) {
        float4 av = *(const float4*)(A + (size_t)lrow * lda + k0 + lcol);
        As[lcol + 0][lrow] = av.x; As[lcol + 1][lrow] = av.y;
        As[lcol + 2][lrow] = av.z; As[lcol + 3][lrow] = av.w;
        *(float4*)&Bs[brow][bcol] = *(const float4*)(B + (size_t)(k0 + brow) * ldb + bcol);
        __syncthreads();

        #pragma unroll
        for (int kk = 0; kk < 8; kk++) {
            float a[8], b[8];
            *(float4*)(a)     = *(const float4*)&As[kk][ty * 4];
            *(float4*)(a + 4) = *(const float4*)&As[kk][64 + ty * 4];
            *(float4*)(b)     = *(const float4*)&Bs[kk][tx * 4];
            *(float4*)(b + 4) = *(const float4*)&Bs[kk][64 + tx * 4];
            #pragma unroll
            for (int i = 0; i < 8; i++)
                #pragma unroll
                for (int j = 0; j < 8; j++)
                    acc[i][j] += a[i] * b[j];
        }
        __syncthreads();
    }

    #pragma unroll
    for (int i = 0; i < 8; i++) {
        int row = (i < 4) ? (ty * 4 + i) : (64 + ty * 4 + (i - 4));
        float* cr = C + (size_t)row * ldc;
        *(float4*)(cr + tx * 4)      = make_float4(acc[i][0], acc[i][1], acc[i][2], acc[i][3]);
        *(float4*)(cr + 64 + tx * 4) = make_float4(acc[i][4], acc[i][5], acc[i][6], acc[i][7]);
    }
}

// ---------------------------------------------------------------------------
// Causal row softmax over scores, in place.  One block per (b, q) row.
// attn = softmax(scores * 1/sqrt(D)) with cols > q masked; zero-fills tail.
// ---------------------------------------------------------------------------
__global__ void __launch_bounds__(256) softmax_causal_kernel(float* __restrict__ S)
{
    int gr = blockIdx.x;            // 0 .. B*S-1
    int b  = gr >> 11;              // /2048
    int q  = gr & 2047;
    float* row = S + ((size_t)b * SS + q) * SS;
    int L = q + 1;
    const float scale = 0.03125f;   // 1/sqrt(1024)

    __shared__ float red[256];
    int tid = threadIdx.x;

    float m = -1e30f;
    for (int i = tid; i < L; i += 256) m = fmaxf(m, row[i]);
    red[tid] = m; __syncthreads();
    #pragma unroll
    for (int s = 128; s > 0; s >>= 1) {
        if (tid < s) red[tid] = fmaxf(red[tid], red[tid + s]);
        __syncthreads();
    }
    m = red[0] * scale;
    __syncthreads();

    float sum = 0.f;
    for (int i = tid; i < L; i += 256) {
        float e = __expf(row[i] * scale - m);
        row[i] = e;
        sum += e;
    }
    red[tid] = sum; __syncthreads();
    #pragma unroll
    for (int s = 128; s > 0; s >>= 1) {
        if (tid < s) red[tid] += red[tid + s];
        __syncthreads();
    }
    float inv = 1.0f / red[0];
    __syncthreads();

    for (int i = tid; i < L; i += 256)       row[i] *= inv;
    for (int i = L + tid; i < SS; i += 256)  row[i] = 0.0f;
}

// ---------------------------------------------------------------------------
extern "C" void kernel_launch(void* const* d_in, const int* in_sizes, int n_in,
                              void* d_out, int out_size)
{
    const float* x  = (const float*)d_in[0];
    const float* Wq = (const float*)d_in[1];
    const float* Wk = (const float*)d_in[2];
    const float* Wv = (const float*)d_in[3];
    float* out = (float*)d_out;

    float *Qp, *Kp, *Vp, *Pp;
    cudaGetSymbolAddress((void**)&Qp, g_Q);
    cudaGetSymbolAddress((void**)&Kp, g_K);
    cudaGetSymbolAddress((void**)&Vp, g_V);
    cudaGetSymbolAddress((void**)&Pp, g_P);

    const size_t sQKV = (size_t)SS * DD;   // per-batch stride of Q/K/V
    const size_t sP   = (size_t)SS * SS;   // per-batch stride of scores

    // 1) QKV projections:  [B*S, D] = x[B*S, D] @ W[D, D]^T
    dim3 gProj(DD / 128, (BB * SS) / 128, 1);
    gemm_nt_kernel<false><<<gProj, 256>>>(x, Wq, Qp, DD, DD, 0, 0, 0);
    gemm_nt_kernel<false><<<gProj, 256>>>(x, Wk, Kp, DD, DD, 0, 0, 0);
    gemm_nt_kernel<false><<<gProj, 256>>>(x, Wv, Vp, DD, DD, 0, 0, 0);

    // 2) Scores: P_b = Q_b @ K_b^T   (skip blocks above diagonal)
    dim3 gScore(SS / 128, SS / 128, BB);
    gemm_nt_kernel<true><<<gScore, 256>>>(Qp, Kp, Pp, DD, SS, sQKV, sQKV, sP);

    // 3) Causal softmax in place
    softmax_causal_kernel<<<BB * SS, 256>>>(Pp);

    // 4) Output: O_b = P_b @ V_b   (k-loop truncated by causality)
    dim3 gOut(DD / 128, SS / 128, BB);
    gemm_nn_kernel<true><<<gOut, 256>>>(Pp, Vp, out, SS, SS, DD, DD, sP, sQKV, sQKV);
}

// round 3
// speedup vs baseline: 2.4392x; 2.4392x over previous
#include <cuda_runtime.h>
#include <cstdint>
#include <cstddef>

#define BB 4
#define SS 2048
#define DD 1024

// Scratch (__device__ globals; allocation-free rule)
__device__ float g_Q[BB * SS * DD];
__device__ float g_K[BB * SS * DD];
__device__ float g_V[BB * SS * DD];
__device__ float g_VT[BB * SS * DD];
__device__ float g_P[(size_t)BB * SS * SS];

__device__ __forceinline__ uint32_t f2tf32(float x) {
    uint32_t y;
    asm("cvt.rna.tf32.f32 %0, %1;" : "=r"(y) : "f"(x));
    return y;
}

__device__ __forceinline__ void mma_tf32(float c[4], uint32_t a0, uint32_t a1,
                                         uint32_t a2, uint32_t a3,
                                         uint32_t b0, uint32_t b1) {
    asm volatile(
        "mma.sync.aligned.m16n8k8.row.col.f32.tf32.tf32.f32 "
        "{%0,%1,%2,%3}, {%4,%5,%6,%7}, {%8,%9}, {%0,%1,%2,%3};\n"
        : "+f"(c[0]), "+f"(c[1]), "+f"(c[2]), "+f"(c[3])
        : "r"(a0), "r"(a1), "r"(a2), "r"(a3), "r"(b0), "r"(b1));
}

// ===================== tf32 NT GEMM =====================
// C[m,n] = sum_k A[m,k] * B[n,k]; A:[M,K] rm, B:[N,K] rm.
// 128x128 CTA tile, BK=16, 256 thr, 8 warps of 64x32, double-buffered smem.
// SKIP_UPPER: skip bx > by (causal scores).  KTRUNC: kend = (by+1)*128 (P·V).
#define BK 16
#define STR 20   // smem row stride (floats): conflict-free fragment LDS

template<bool SKIP_UPPER, bool KTRUNC>
__global__ void __launch_bounds__(256) mm_tc(
    const float* __restrict__ Ab, const float* __restrict__ Bb, float* __restrict__ Cb,
    int K, int lda, int ldb, int ldc, size_t sA, size_t sB, size_t sC)
{
    const int bx = blockIdx.x, by = blockIdx.y;
    if (SKIP_UPPER && bx > by) return;

    __shared__ float sm[4][128 * STR];   // [buf*2 + op][row*STR + k]

    const int tid  = threadIdx.x;
    const int wid  = tid >> 5, lane = tid & 31;
    const int wm   = wid & 1;            // warp row (0..1) -> 64 rows
    const int wn   = wid >> 1;           // warp col (0..3) -> 32 cols
    const int gid  = lane >> 2;          // 0..7
    const int tig  = lane & 3;           // 0..3

    const float* A = Ab + blockIdx.z * sA + (size_t)by * 128 * lda;
    const float* B = Bb + blockIdx.z * sB + (size_t)bx * 128 * ldb;
    float*       C = Cb + blockIdx.z * sC + (size_t)by * 128 * ldc + (size_t)bx * 128;

    const int kend = KTRUNC ? min(K, (by + 1) * 128) : K;
    const int NC   = kend / BK;

    // fill indices: thread covers rows r and r+64, float4 segment f of BK
    const int r = tid >> 2;
    const int f = tid & 3;

    float4 stg[4];  // A@r, A@r+64, B@r, B@r+64

    auto ldg_chunk = [&](int k0) {
        stg[0] = *(const float4*)(A + (size_t)r        * lda + k0 + f * 4);
        stg[1] = *(const float4*)(A + (size_t)(r + 64) * lda + k0 + f * 4);
        stg[2] = *(const float4*)(B + (size_t)r        * ldb + k0 + f * 4);
        stg[3] = *(const float4*)(B + (size_t)(r + 64) * ldb + k0 + f * 4);
    };
    auto sts_chunk = [&](int buf) {
        float* as = sm[buf * 2 + 0];
        float* bs = sm[buf * 2 + 1];
        #pragma unroll
        for (int h = 0; h < 2; h++) {
            int row = r + h * 64;
            float4 va = stg[h], vb = stg[2 + h];
            as[row * STR + f * 4 + 0] = __uint_as_float(f2tf32(va.x));
            as[row * STR + f * 4 + 1] = __uint_as_float(f2tf32(va.y));
            as[row * STR + f * 4 + 2] = __uint_as_float(f2tf32(va.z));
            as[row * STR + f * 4 + 3] = __uint_as_float(f2tf32(va.w));
            bs[row * STR + f * 4 + 0] = __uint_as_float(f2tf32(vb.x));
            bs[row * STR + f * 4 + 1] = __uint_as_float(f2tf32(vb.y));
            bs[row * STR + f * 4 + 2] = __uint_as_float(f2tf32(vb.z));
            bs[row * STR + f * 4 + 3] = __uint_as_float(f2tf32(vb.w));
        }
    };

    float acc[4][4][4];
    #pragma unroll
    for (int i = 0; i < 4; i++)
        #pragma unroll
        for (int j = 0; j < 4; j++)
            #pragma unroll
            for (int t = 0; t < 4; t++) acc[i][j][t] = 0.f;

    ldg_chunk(0);
    sts_chunk(0);
    __syncthreads();

    for (int c = 0; c < NC; c++) {
        if (c + 1 < NC) ldg_chunk((c + 1) * BK);

        const float* as = sm[(c & 1) * 2 + 0];
        const float* bs = sm[(c & 1) * 2 + 1];
        #pragma unroll
        for (int ks = 0; ks < BK; ks += 8) {
            uint32_t afr[4][4], bfr[4][2];
            #pragma unroll
            for (int mt = 0; mt < 4; mt++) {
                int row = wm * 64 + mt * 16 + gid;
                int k   = ks + tig;
                afr[mt][0] = __float_as_uint(as[row       * STR + k]);
                afr[mt][1] = __float_as_uint(as[(row + 8) * STR + k]);
                afr[mt][2] = __float_as_uint(as[row       * STR + k + 4]);
                afr[mt][3] = __float_as_uint(as[(row + 8) * STR + k + 4]);
            }
            #pragma unroll
            for (int nt = 0; nt < 4; nt++) {
                int col = wn * 32 + nt * 8 + gid;
                int k   = ks + tig;
                bfr[nt][0] = __float_as_uint(bs[col * STR + k]);
                bfr[nt][1] = __float_as_uint(bs[col * STR + k + 4]);
            }
            #pragma unroll
            for (int mt = 0; mt < 4; mt++)
                #pragma unroll
                for (int nt = 0; nt < 4; nt++)
                    mma_tf32(acc[mt][nt], afr[mt][0], afr[mt][1], afr[mt][2],
                             afr[mt][3], bfr[nt][0], bfr[nt][1]);
        }
        __syncthreads();
        if (c + 1 < NC) {
            sts_chunk((c + 1) & 1);
            __syncthreads();
        }
    }

    // Epilogue: direct STG.64 per (mt, nt) fragment
    #pragma unroll
    for (int mt = 0; mt < 4; mt++) {
        int row0 = wm * 64 + mt * 16 + gid;
        #pragma unroll
        for (int nt = 0; nt < 4; nt++) {
            int col0 = wn * 32 + nt * 8 + tig * 2;
            *(float2*)(C + (size_t)row0       * ldc + col0) =
                make_float2(acc[mt][nt][0], acc[mt][nt][1]);
            *(float2*)(C + (size_t)(row0 + 8) * ldc + col0) =
                make_float2(acc[mt][nt][2], acc[mt][nt][3]);
        }
    }
}

// ===================== V -> V^T transpose (per batch) ========================
__global__ void __launch_bounds__(256) transpose_kernel(
    const float* __restrict__ V, float* __restrict__ VT)
{
    __shared__ float t[32][33];
    int z = blockIdx.z;
    const float* Vb = V + (size_t)z * SS * DD;
    float* VTb = VT + (size_t)z * SS * DD;
    int d0 = blockIdx.x * 32, s0 = blockIdx.y * 32;
    int tx = threadIdx.x & 31, ty = threadIdx.x >> 5;   // 32 x 8
    #pragma unroll
    for (int j = 0; j < 4; j++)
        t[ty + j * 8][tx] = Vb[(size_t)(s0 + ty + j * 8) * DD + d0 + tx];
    __syncthreads();
    #pragma unroll
    for (int j = 0; j < 4; j++)
        VTb[(size_t)(d0 + ty + j * 8) * SS + s0 + tx] = t[tx][ty + j * 8];
}

// ===================== causal softmax (in place) =============================
__global__ void __launch_bounds__(256) softmax_causal_kernel(float* __restrict__ S)
{
    int gr = blockIdx.x;
    int b  = gr >> 11;
    int q  = gr & 2047;
    float* row = S + ((size_t)b * SS + q) * SS;
    int L = q + 1;
    const float scale = 0.03125f;   // 1/sqrt(1024)

    __shared__ float red[256];
    int tid = threadIdx.x;

    float m = -1e30f;
    for (int i = tid; i < L; i += 256) m = fmaxf(m, row[i]);
    red[tid] = m; __syncthreads();
    #pragma unroll
    for (int s = 128; s > 0; s >>= 1) {
        if (tid < s) red[tid] = fmaxf(red[tid], red[tid + s]);
        __syncthreads();
    }
    m = red[0] * scale;
    __syncthreads();

    float sum = 0.f;
    for (int i = tid; i < L; i += 256) {
        float e = __expf(row[i] * scale - m);
        row[i] = e;
        sum += e;
    }
    red[tid] = sum; __syncthreads();
    #pragma unroll
    for (int s = 128; s > 0; s >>= 1) {
        if (tid < s) red[tid] += red[tid + s];
        __syncthreads();
    }
    float inv = 1.0f / red[0];
    __syncthreads();

    for (int i = tid; i < L; i += 256)       row[i] *= inv;
    for (int i = L + tid; i < SS; i += 256)  row[i] = 0.0f;
}

// ===========================================================================
extern "C" void kernel_launch(void* const* d_in, const int* in_sizes, int n_in,
                              void* d_out, int out_size)
{
    const float* x  = (const float*)d_in[0];
    const float* Wq = (const float*)d_in[1];
    const float* Wk = (const float*)d_in[2];
    const float* Wv = (const float*)d_in[3];
    float* out = (float*)d_out;

    float *Qp, *Kp, *Vp, *VTp, *Pp;
    cudaGetSymbolAddress((void**)&Qp,  g_Q);
    cudaGetSymbolAddress((void**)&Kp,  g_K);
    cudaGetSymbolAddress((void**)&Vp,  g_V);
    cudaGetSymbolAddress((void**)&VTp, g_VT);
    cudaGetSymbolAddress((void**)&Pp,  g_P);

    const size_t sQKV = (size_t)SS * DD;
    const size_t sP   = (size_t)SS * SS;

    // 1) QKV projections: [8192, 1024] = x @ W^T  (NT, W rows are n)
    dim3 gProj(DD / 128, (BB * SS) / 128, 1);
    mm_tc<false, false><<<gProj, 256>>>(x, Wq, Qp, DD, DD, DD, DD, 0, 0, 0);
    mm_tc<false, false><<<gProj, 256>>>(x, Wk, Kp, DD, DD, DD, DD, 0, 0, 0);
    mm_tc<false, false><<<gProj, 256>>>(x, Wv, Vp, DD, DD, DD, DD, 0, 0, 0);

    // 2) V -> V^T (so P·V is NT too)
    dim3 gT(DD / 32, SS / 32, BB);
    transpose_kernel<<<gT, 256>>>(Vp, VTp);

    // 3) Scores: P_b = Q_b @ K_b^T  (skip strictly-upper tiles)
    dim3 gScore(SS / 128, SS / 128, BB);
    mm_tc<true, false><<<gScore, 256>>>(Qp, Kp, Pp, DD, DD, DD, SS, sQKV, sQKV, sP);

    // 4) Causal softmax in place
    softmax_causal_kernel<<<BB * SS, 256>>>(Pp);

    // 5) O_b = P_b @ (V^T_b)^T  (K truncated by causality)
    dim3 gOut(DD / 128, SS / 128, BB);
    mm_tc<false, true><<<gOut, 256>>>(Pp, VTp, out, SS, SS, SS, DD, sP, sQKV, sQKV);
}

// round 4
// speedup vs baseline: 2.8134x; 1.1534x over previous
#include <cuda_runtime.h>
#include <cstdint>
#include <cstddef>

#define BB 4
#define SS 2048
#define DD 1024

// Scratch (__device__ globals; allocation-free rule)
__device__ float g_X[BB * SS * DD];
__device__ float g_Wq[DD * DD];
__device__ float g_Wk[DD * DD];
__device__ float g_Wv[DD * DD];
__device__ float g_Q[BB * SS * DD];
__device__ float g_K[BB * SS * DD];
__device__ float g_V[BB * SS * DD];
__device__ float g_VT[BB * SS * DD];
__device__ float g_P[(size_t)BB * SS * SS];

__device__ __forceinline__ uint32_t smem_u32(const void* p) {
    uint32_t a;
    asm("{ .reg .u64 t; cvta.to.shared.u64 t, %1; cvt.u32.u64 %0, t; }" : "=r"(a) : "l"(p));
    return a;
}
__device__ __forceinline__ uint32_t f2tf32(float x) {
    uint32_t y;
    asm("cvt.rna.tf32.f32 %0, %1;" : "=r"(y) : "f"(x));
    return y;
}
__device__ __forceinline__ void cp16(uint32_t dst, const void* src) {
    asm volatile("cp.async.cg.shared.global [%0], [%1], 16;" :: "r"(dst), "l"(src) : "memory");
}
__device__ __forceinline__ void mma_tf32(float c[4], uint32_t a0, uint32_t a1,
                                         uint32_t a2, uint32_t a3,
                                         uint32_t b0, uint32_t b1) {
    asm volatile(
        "mma.sync.aligned.m16n8k8.row.col.f32.tf32.tf32.f32 "
        "{%0,%1,%2,%3}, {%4,%5,%6,%7}, {%8,%9}, {%0,%1,%2,%3};\n"
        : "+f"(c[0]), "+f"(c[1]), "+f"(c[2]), "+f"(c[3])
        : "r"(a0), "r"(a1), "r"(a2), "r"(a3), "r"(b0), "r"(b1));
}

// ===================== tf32 NT GEMM (operands pre-rounded to tf32) ==========
// C[m,n] = sum_k A[m,k] * B[n,k]; A:[M,K] rm, B:[N,K] rm.
// 128x128 CTA tile, BK=16, 256 thr (8 warps of 64x32), 4-stage cp.async ring.
// SKIP_UPPER: skip bx > by (causal scores).  KTRUNC: kend = (by+1)*128 (P·V).
// ROUND_OUT: round outputs to tf32 (for Q/K/V that feed later GEMMs).
#define BK 16
#define STR 20                 // smem row stride (floats): conflict-free LDS
#define STAGES 4
#define STG_BYTES (128 * STR * 4 * 2)      // 20480: A tile + B tile per stage
#define SMEM_BYTES (STAGES * STG_BYTES)    // 81920

template<bool SKIP_UPPER, bool KTRUNC, bool ROUND_OUT>
__global__ void __launch_bounds__(256) mm_tc(
    const float* __restrict__ Ab, const float* __restrict__ Bb, float* __restrict__ Cb,
    int K, int lda, int ldb, int ldc, size_t sA, size_t sB, size_t sC)
{
    const int bx = blockIdx.x, by = blockIdx.y;
    if (SKIP_UPPER && bx > by) return;

    extern __shared__ __align__(128) char smem[];
    const uint32_t sb = smem_u32(smem);

    const int tid  = threadIdx.x;
    const int wid  = tid >> 5, lane = tid & 31;
    const int wm   = wid & 1;            // warp row (0..1) -> 64 rows
    const int wn   = wid >> 1;           // warp col (0..3) -> 32 cols
    const int gid  = lane >> 2;          // 0..7
    const int tig  = lane & 3;           // 0..3

    const float* A = Ab + blockIdx.z * sA + (size_t)by * 128 * lda;
    const float* B = Bb + blockIdx.z * sB + (size_t)bx * 128 * ldb;
    float*       C = Cb + blockIdx.z * sC + (size_t)by * 128 * ldc + (size_t)bx * 128;

    const int kend = KTRUNC ? min(K, (by + 1) * 128) : K;
    const int NC   = kend / BK;          // >= 8 always

    // issue one K-chunk's cp.asyncs (A+B tiles) into stage c%STAGES
    auto issue_chunk = [&](int c) {
        const uint32_t ab = sb + (c & (STAGES - 1)) * STG_BYTES;
        const uint32_t bb = ab + 128 * STR * 4;
        const int k0 = c * BK;
        #pragma unroll
        for (int i = 0; i < 2; i++) {
            int s = tid + i * 256;       // 512 16B-segments per operand
            int r = s >> 2, f = s & 3;
            uint32_t d = r * (STR * 4) + f * 16;
            cp16(ab + d, A + (size_t)r * lda + k0 + f * 4);
            cp16(bb + d, B + (size_t)r * ldb + k0 + f * 4);
        }
        asm volatile("cp.async.commit_group;" ::: "memory");
    };

    float acc[4][4][4];
    #pragma unroll
    for (int i = 0; i < 4; i++)
        #pragma unroll
        for (int j = 0; j < 4; j++)
            #pragma unroll
            for (int t = 0; t < 4; t++) acc[i][j][t] = 0.f;

    // prologue: STAGES-1 chunks in flight
    issue_chunk(0); issue_chunk(1); issue_chunk(2);

    for (int c = 0; c < NC; c++) {
        asm volatile("cp.async.wait_group 2;" ::: "memory");   // chunk c arrived
        __syncthreads();
        if (c + 3 < NC) issue_chunk(c + 3);
        else asm volatile("cp.async.commit_group;" ::: "memory");  // keep count uniform

        const float* as = (const float*)(smem + (c & (STAGES - 1)) * STG_BYTES);
        const float* bs = as + 128 * STR;

        #pragma unroll
        for (int ks = 0; ks < BK; ks += 8) {
            uint32_t afr[4][4], bfr[4][2];
            #pragma unroll
            for (int mt = 0; mt < 4; mt++) {
                int row = wm * 64 + mt * 16 + gid;
                int k   = ks + tig;
                afr[mt][0] = __float_as_uint(as[row       * STR + k]);
                afr[mt][1] = __float_as_uint(as[(row + 8) * STR + k]);
                afr[mt][2] = __float_as_uint(as[row       * STR + k + 4]);
                afr[mt][3] = __float_as_uint(as[(row + 8) * STR + k + 4]);
            }
            #pragma unroll
            for (int nt = 0; nt < 4; nt++) {
                int col = wn * 32 + nt * 8 + gid;
                int k   = ks + tig;
                bfr[nt][0] = __float_as_uint(bs[col * STR + k]);
                bfr[nt][1] = __float_as_uint(bs[col * STR + k + 4]);
            }
            #pragma unroll
            for (int mt = 0; mt < 4; mt++)
                #pragma unroll
                for (int nt = 0; nt < 4; nt++)
                    mma_tf32(acc[mt][nt], afr[mt][0], afr[mt][1], afr[mt][2],
                             afr[mt][3], bfr[nt][0], bfr[nt][1]);
        }
    }

    // Epilogue: direct STG.64 per fragment (optionally tf32-rounded)
    #pragma unroll
    for (int mt = 0; mt < 4; mt++) {
        int row0 = wm * 64 + mt * 16 + gid;
        #pragma unroll
        for (int nt = 0; nt < 4; nt++) {
            int col0 = wn * 32 + nt * 8 + tig * 2;
            float v0 = acc[mt][nt][0], v1 = acc[mt][nt][1];
            float v2 = acc[mt][nt][2], v3 = acc[mt][nt][3];
            if (ROUND_OUT) {
                v0 = __uint_as_float(f2tf32(v0)); v1 = __uint_as_float(f2tf32(v1));
                v2 = __uint_as_float(f2tf32(v2)); v3 = __uint_as_float(f2tf32(v3));
            }
            *(float2*)(C + (size_t)row0       * ldc + col0) = make_float2(v0, v1);
            *(float2*)(C + (size_t)(row0 + 8) * ldc + col0) = make_float2(v2, v3);
        }
    }
}

// ===================== elementwise tf32 pre-round ============================
__global__ void __launch_bounds__(256) round4_kernel(
    const float* __restrict__ in, float* __restrict__ out)
{
    size_t i = (size_t)blockIdx.x * 256 + threadIdx.x;
    float4 v = ((const float4*)in)[i];
    v.x = __uint_as_float(f2tf32(v.x));
    v.y = __uint_as_float(f2tf32(v.y));
    v.z = __uint_as_float(f2tf32(v.z));
    v.w = __uint_as_float(f2tf32(v.w));
    ((float4*)out)[i] = v;
}

// ===================== V -> V^T transpose (per batch) ========================
__global__ void __launch_bounds__(256) transpose_kernel(
    const float* __restrict__ V, float* __restrict__ VT)
{
    __shared__ float t[32][33];
    int z = blockIdx.z;
    const float* Vb = V + (size_t)z * SS * DD;
    float* VTb = VT + (size_t)z * SS * DD;
    int d0 = blockIdx.x * 32, s0 = blockIdx.y * 32;
    int tx = threadIdx.x & 31, ty = threadIdx.x >> 5;   // 32 x 8
    #pragma unroll
    for (int j = 0; j < 4; j++)
        t[ty + j * 8][tx] = Vb[(size_t)(s0 + ty + j * 8) * DD + d0 + tx];
    __syncthreads();
    #pragma unroll
    for (int j = 0; j < 4; j++)
        VTb[(size_t)(d0 + ty + j * 8) * SS + s0 + tx] = t[tx][ty + j * 8];
}

// ===================== causal softmax (in place, rounds P to tf32) ===========
__global__ void __launch_bounds__(256) softmax_causal_kernel(float* __restrict__ S)
{
    int gr = blockIdx.x;
    int b  = gr >> 11;
    int q  = gr & 2047;
    float* row = S + ((size_t)b * SS + q) * SS;
    int L = q + 1;
    const float scale = 0.03125f;   // 1/sqrt(1024)

    __shared__ float red[256];
    int tid = threadIdx.x;

    float m = -1e30f;
    for (int i = tid; i < L; i += 256) m = fmaxf(m, row[i]);
    red[tid] = m; __syncthreads();
    #pragma unroll
    for (int s = 128; s > 0; s >>= 1) {
        if (tid < s) red[tid] = fmaxf(red[tid], red[tid + s]);
        __syncthreads();
    }
    m = red[0] * scale;
    __syncthreads();

    float sum = 0.f;
    for (int i = tid; i < L; i += 256) {
        float e = __expf(row[i] * scale - m);
        row[i] = e;
        sum += e;
    }
    red[tid] = sum; __syncthreads();
    #pragma unroll
    for (int s = 128; s > 0; s >>= 1) {
        if (tid < s) red[tid] += red[tid + s];
        __syncthreads();
    }
    float inv = 1.0f / red[0];
    __syncthreads();

    for (int i = tid; i < L; i += 256)
        row[i] = __uint_as_float(f2tf32(row[i] * inv));
    for (int i = L + tid; i < SS; i += 256)  row[i] = 0.0f;
}

// ===========================================================================
extern "C" void kernel_launch(void* const* d_in, const int* in_sizes, int n_in,
                              void* d_out, int out_size)
{
    const float* x  = (const float*)d_in[0];
    const float* Wq = (const float*)d_in[1];
    const float* Wk = (const float*)d_in[2];
    const float* Wv = (const float*)d_in[3];
    float* out = (float*)d_out;

    float *Xp, *Wqp, *Wkp, *Wvp, *Qp, *Kp, *Vp, *VTp, *Pp;
    cudaGetSymbolAddress((void**)&Xp,  g_X);
    cudaGetSymbolAddress((void**)&Wqp, g_Wq);
    cudaGetSymbolAddress((void**)&Wkp, g_Wk);
    cudaGetSymbolAddress((void**)&Wvp, g_Wv);
    cudaGetSymbolAddress((void**)&Qp,  g_Q);
    cudaGetSymbolAddress((void**)&Kp,  g_K);
    cudaGetSymbolAddress((void**)&Vp,  g_V);
    cudaGetSymbolAddress((void**)&VTp, g_VT);
    cudaGetSymbolAddress((void**)&Pp,  g_P);

    cudaFuncSetAttribute(mm_tc<false, false, true>,
                         cudaFuncAttributeMaxDynamicSharedMemorySize, SMEM_BYTES);
    cudaFuncSetAttribute(mm_tc<true, false, false>,
                         cudaFuncAttributeMaxDynamicSharedMemorySize, SMEM_BYTES);
    cudaFuncSetAttribute(mm_tc<false, true, false>,
                         cudaFuncAttributeMaxDynamicSharedMemorySize, SMEM_BYTES);

    const size_t sQKV = (size_t)SS * DD;
    const size_t sP   = (size_t)SS * SS;

    // 0) pre-round inputs to tf32 (so GEMMs need no cvt in the mainloop)
    round4_kernel<<<(BB * SS * DD) / 4 / 256, 256>>>(x,  Xp);
    round4_kernel<<<(DD * DD) / 4 / 256, 256>>>(Wq, Wqp);
    round4_kernel<<<(DD * DD) / 4 / 256, 256>>>(Wk, Wkp);
    round4_kernel<<<(DD * DD) / 4 / 256, 256>>>(Wv, Wvp);

    // 1) QKV projections (outputs rounded to tf32)
    dim3 gProj(DD / 128, (BB * SS) / 128, 1);
    mm_tc<false, false, true><<<gProj, 256, SMEM_BYTES>>>(Xp, Wqp, Qp, DD, DD, DD, DD, 0, 0, 0);
    mm_tc<false, false, true><<<gProj, 256, SMEM_BYTES>>>(Xp, Wkp, Kp, DD, DD, DD, DD, 0, 0, 0);
    mm_tc<false, false, true><<<gProj, 256, SMEM_BYTES>>>(Xp, Wvp, Vp, DD, DD, DD, DD, 0, 0, 0);

    // 2) V -> V^T (so P·V is NT too)
    dim3 gT(DD / 32, SS / 32, BB);
    transpose_kernel<<<gT, 256>>>(Vp, VTp);

    // 3) Scores: P_b = Q_b @ K_b^T  (skip strictly-upper tiles)
    dim3 gScore(SS / 128, SS / 128, BB);
    mm_tc<true, false, false><<<gScore, 256, SMEM_BYTES>>>(Qp, Kp, Pp, DD, DD, DD, SS,
                                                           sQKV, sQKV, sP);

    // 4) Causal softmax in place (rounds P to tf32)
    softmax_causal_kernel<<<BB * SS, 256>>>(Pp);

    // 5) O_b = P_b @ (V^T_b)^T  (K truncated by causality)
    dim3 gOut(DD / 128, SS / 128, BB);
    mm_tc<false, true, false><<<gOut, 256, SMEM_BYTES>>>(Pp, VTp, out, SS, SS, SS, DD,
                                                         sP, sQKV, sQKV);
}

// round 5
// speedup vs baseline: 5.8761x; 2.0886x over previous
#include <cuda_runtime.h>
#include <cuda_fp16.h>
#include <cstdint>
#include <cstddef>

#define BB 4
#define SS 2048
#define DD 1024

// Scratch (__device__ globals; allocation-free rule)
__device__ __half g_X16[BB * SS * DD];
__device__ __half g_Wq16[DD * DD];
__device__ __half g_Wk16[DD * DD];
__device__ __half g_Wv16[DD * DD];
__device__ __half g_Q16[BB * SS * DD];
__device__ __half g_K16[BB * SS * DD];
__device__ __half g_V16[BB * SS * DD];
__device__ __half g_VT16[BB * SS * DD];
__device__ float  g_P[(size_t)BB * SS * SS];     // fp32 scores
__device__ __half g_P16[(size_t)BB * SS * SS];   // fp16 probabilities

__device__ __forceinline__ uint32_t smem_u32(const void* p) {
    uint32_t a;
    asm("{ .reg .u64 t; cvta.to.shared.u64 t, %1; cvt.u32.u64 %0, t; }" : "=r"(a) : "l"(p));
    return a;
}
__device__ __forceinline__ void cp16(uint32_t dst, const void* src) {
    asm volatile("cp.async.cg.shared.global [%0], [%1], 16;" :: "r"(dst), "l"(src) : "memory");
}
__device__ __forceinline__ void ldsm_x4(uint32_t& r0, uint32_t& r1, uint32_t& r2,
                                        uint32_t& r3, uint32_t addr) {
    asm volatile("ldmatrix.sync.aligned.m8n8.x4.shared.b16 {%0,%1,%2,%3}, [%4];"
                 : "=r"(r0), "=r"(r1), "=r"(r2), "=r"(r3) : "r"(addr));
}
__device__ __forceinline__ void mma_fp16(float c[4], uint32_t a0, uint32_t a1,
                                         uint32_t a2, uint32_t a3,
                                         uint32_t b0, uint32_t b1) {
    asm volatile(
        "mma.sync.aligned.m16n8k16.row.col.f32.f16.f16.f32 "
        "{%0,%1,%2,%3}, {%4,%5,%6,%7}, {%8,%9}, {%0,%1,%2,%3};\n"
        : "+f"(c[0]), "+f"(c[1]), "+f"(c[2]), "+f"(c[3])
        : "r"(a0), "r"(a1), "r"(a2), "r"(a3), "r"(b0), "r"(b1));
}

// ===================== fp16 NT GEMM =====================
// C[m,n] = sum_k A[m,k]*B[n,k]; A:[M,K] rm fp16, B:[N,K] rm fp16.
// 128x128 CTA tile, BK=32, 256 thr (8 warps of 64x32), 4-stage cp.async ring,
// ldmatrix.x4 fragment loads. Smem row stride 80B (conflict-free phases).
#define BK 32
#define ROWB 80                       // bytes per smem row (32 halves + pad)
#define OPB (128 * ROWB)              // 10240 bytes per operand tile
#define STG_BYTES (2 * OPB)           // 20480 per stage
#define STAGES 4
#define SMEM_BYTES (STAGES * STG_BYTES)

template<bool SKIP_UPPER, bool KTRUNC, bool OUT_HALF>
__global__ void __launch_bounds__(256) mm_fp16(
    const __half* __restrict__ Ab, const __half* __restrict__ Bb, void* __restrict__ Cb,
    int K, int lda, int ldb, int ldc, size_t sA, size_t sB, size_t sC)
{
    const int bx = blockIdx.x, by = blockIdx.y;
    if (SKIP_UPPER && bx > by) return;

    extern __shared__ __align__(128) char smem[];
    const uint32_t sb = smem_u32(smem);

    const int tid  = threadIdx.x;
    const int wid  = tid >> 5, lane = tid & 31;
    const int wm   = wid & 1;            // warp row -> 64 rows
    const int wn   = wid >> 1;           // warp col -> 32 cols
    const int gid  = lane >> 2;
    const int tig  = lane & 3;

    const __half* A = Ab + blockIdx.z * sA + (size_t)by * 128 * lda;
    const __half* B = Bb + blockIdx.z * sB + (size_t)bx * 128 * ldb;

    const int kend = KTRUNC ? min(K, (by + 1) * 128) : K;
    const int NC   = kend / BK;          // >= 4 always

    // ldmatrix lane-address offsets (within operand tile)
    const uint32_t aoff = (uint32_t)(wm * 64 + (lane & 15)) * ROWB + (lane >> 4) * 16;
    const int lrow_b = (lane & 7) + ((lane >> 4) << 3);
    const int lcol_b = ((lane >> 3) & 1) * 16;
    const uint32_t boff = (uint32_t)(wn * 32 + lrow_b) * ROWB + lcol_b;

    auto issue_chunk = [&](int c) {
        const uint32_t ab = sb + (c & (STAGES - 1)) * STG_BYTES;
        const uint32_t bb = ab + OPB;
        const int k0 = c * BK;
        #pragma unroll
        for (int i = 0; i < 2; i++) {
            int s = tid + i * 256;       // 512 16B segs per operand
            int r = s >> 2, f = s & 3;
            uint32_t d = r * ROWB + f * 16;
            cp16(ab + d, A + (size_t)r * lda + k0 + f * 8);
            cp16(bb + d, B + (size_t)r * ldb + k0 + f * 8);
        }
        asm volatile("cp.async.commit_group;" ::: "memory");
    };

    float acc[4][4][4];
    #pragma unroll
    for (int i = 0; i < 4; i++)
        #pragma unroll
        for (int j = 0; j < 4; j++)
            #pragma unroll
            for (int t = 0; t < 4; t++) acc[i][j][t] = 0.f;

    issue_chunk(0); issue_chunk(1); issue_chunk(2);

    for (int c = 0; c < NC; c++) {
        asm volatile("cp.async.wait_group 2;" ::: "memory");
        __syncthreads();
        if (c + 3 < NC) issue_chunk(c + 3);
        else asm volatile("cp.async.commit_group;" ::: "memory");

        const uint32_t ab = sb + (c & (STAGES - 1)) * STG_BYTES;
        const uint32_t bb = ab + OPB;

        #pragma unroll
        for (int ks = 0; ks < 2; ks++) {     // two k16 steps per BK=32
            uint32_t afr[4][4], bfr[2][4];
            #pragma unroll
            for (int mt = 0; mt < 4; mt++)
                ldsm_x4(afr[mt][0], afr[mt][1], afr[mt][2], afr[mt][3],
                        ab + aoff + mt * (16 * ROWB) + ks * 32);
            #pragma unroll
            for (int nt2 = 0; nt2 < 2; nt2++)
                ldsm_x4(bfr[nt2][0], bfr[nt2][1], bfr[nt2][2], bfr[nt2][3],
                        bb + boff + nt2 * (16 * ROWB) + ks * 32);
            #pragma unroll
            for (int mt = 0; mt < 4; mt++)
                #pragma unroll
                for (int nt = 0; nt < 4; nt++)
                    mma_fp16(acc[mt][nt], afr[mt][0], afr[mt][1], afr[mt][2],
                             afr[mt][3], bfr[nt >> 1][(nt & 1) * 2],
                             bfr[nt >> 1][(nt & 1) * 2 + 1]);
        }
    }

    // Epilogue
    if (OUT_HALF) {
        __half* C = (__half*)Cb + blockIdx.z * sC + (size_t)by * 128 * ldc
                  + (size_t)bx * 128;
        #pragma unroll
        for (int mt = 0; mt < 4; mt++) {
            int row0 = wm * 64 + mt * 16 + gid;
            #pragma unroll
            for (int nt = 0; nt < 4; nt++) {
                int col0 = wn * 32 + nt * 8 + tig * 2;
                *(__half2*)(C + (size_t)row0       * ldc + col0) =
                    __floats2half2_rn(acc[mt][nt][0], acc[mt][nt][1]);
                *(__half2*)(C + (size_t)(row0 + 8) * ldc + col0) =
                    __floats2half2_rn(acc[mt][nt][2], acc[mt][nt][3]);
            }
        }
    } else {
        float* C = (float*)Cb + blockIdx.z * sC + (size_t)by * 128 * ldc
                 + (size_t)bx * 128;
        #pragma unroll
        for (int mt = 0; mt < 4; mt++) {
            int row0 = wm * 64 + mt * 16 + gid;
            #pragma unroll
            for (int nt = 0; nt < 4; nt++) {
                int col0 = wn * 32 + nt * 8 + tig * 2;
                *(float2*)(C + (size_t)row0       * ldc + col0) =
                    make_float2(acc[mt][nt][0], acc[mt][nt][1]);
                *(float2*)(C + (size_t)(row0 + 8) * ldc + col0) =
                    make_float2(acc[mt][nt][2], acc[mt][nt][3]);
            }
        }
    }
}

// ===================== fp32 -> fp16 convert (4 elts/thread) ==================
__global__ void __launch_bounds__(256) cvtf2h_kernel(
    const float* __restrict__ in, __half* __restrict__ out)
{
    size_t i = (size_t)blockIdx.x * 256 + threadIdx.x;
    float4 v = ((const float4*)in)[i];
    __half2 h0 = __floats2half2_rn(v.x, v.y);
    __half2 h1 = __floats2half2_rn(v.z, v.w);
    ((__half2*)out)[i * 2]     = h0;
    ((__half2*)out)[i * 2 + 1] = h1;
}

// ===================== V16 -> V16^T transpose (per batch) ====================
__global__ void __launch_bounds__(256) transpose16_kernel(
    const __half* __restrict__ V, __half* __restrict__ VT)
{
    __shared__ __half t[32][34];
    int z = blockIdx.z;
    const __half* Vb = V + (size_t)z * SS * DD;
    __half* VTb = VT + (size_t)z * SS * DD;
    int d0 = blockIdx.x * 32, s0 = blockIdx.y * 32;
    int tx = threadIdx.x & 31, ty = threadIdx.x >> 5;   // 32 x 8
    #pragma unroll
    for (int j = 0; j < 4; j++)
        t[ty + j * 8][tx] = Vb[(size_t)(s0 + ty + j * 8) * DD + d0 + tx];
    __syncthreads();
    #pragma unroll
    for (int j = 0; j < 4; j++)
        VTb[(size_t)(d0 + ty + j * 8) * SS + s0 + tx] = t[tx][ty + j * 8];
}

// ===================== causal softmax: fp32 scores -> fp16 probs =============
__global__ void __launch_bounds__(256) softmax_causal_kernel(
    const float* __restrict__ S, __half* __restrict__ P16)
{
    int gr = blockIdx.x;
    int b  = gr >> 11;
    int q  = gr & 2047;
    const float* row = S + ((size_t)b * SS + q) * SS;
    __half* orow = P16 + ((size_t)b * SS + q) * SS;
    int L = q + 1;
    const float scale = 0.03125f;   // 1/sqrt(1024)

    __shared__ float red[256];
    int tid = threadIdx.x;

    float m = -1e30f;
    for (int i = tid; i < L; i += 256) m = fmaxf(m, row[i]);
    red[tid] = m; __syncthreads();
    #pragma unroll
    for (int s = 128; s > 0; s >>= 1) {
        if (tid < s) red[tid] = fmaxf(red[tid], red[tid + s]);
        __syncthreads();
    }
    m = red[0] * scale;
    __syncthreads();

    float sum = 0.f;
    for (int i = tid; i < L; i += 256)
        sum += __expf(row[i] * scale - m);
    red[tid] = sum; __syncthreads();
    #pragma unroll
    for (int s = 128; s > 0; s >>= 1) {
        if (tid < s) red[tid] += red[tid + s];
        __syncthreads();
    }
    float inv = 1.0f / red[0];
    __syncthreads();

    for (int i = tid; i < L; i += 256)
        orow[i] = __float2half_rn(__expf(row[i] * scale - m) * inv);
    for (int i = L + tid; i < SS; i += 256)
        orow[i] = __float2half_rn(0.0f);
}

// ===========================================================================
extern "C" void kernel_launch(void* const* d_in, const int* in_sizes, int n_in,
                              void* d_out, int out_size)
{
    const float* x  = (const float*)d_in[0];
    const float* Wq = (const float*)d_in[1];
    const float* Wk = (const float*)d_in[2];
    const float* Wv = (const float*)d_in[3];
    float* out = (float*)d_out;

    __half *X16, *Wq16, *Wk16, *Wv16, *Q16, *K16, *V16, *VT16, *P16;
    float *Pp;
    cudaGetSymbolAddress((void**)&X16,  g_X16);
    cudaGetSymbolAddress((void**)&Wq16, g_Wq16);
    cudaGetSymbolAddress((void**)&Wk16, g_Wk16);
    cudaGetSymbolAddress((void**)&Wv16, g_Wv16);
    cudaGetSymbolAddress((void**)&Q16,  g_Q16);
    cudaGetSymbolAddress((void**)&K16,  g_K16);
    cudaGetSymbolAddress((void**)&V16,  g_V16);
    cudaGetSymbolAddress((void**)&VT16, g_VT16);
    cudaGetSymbolAddress((void**)&P16,  g_P16);
    cudaGetSymbolAddress((void**)&Pp,   g_P);

    cudaFuncSetAttribute(mm_fp16<false, false, true>,
                         cudaFuncAttributeMaxDynamicSharedMemorySize, SMEM_BYTES);
    cudaFuncSetAttribute(mm_fp16<true, false, false>,
                         cudaFuncAttributeMaxDynamicSharedMemorySize, SMEM_BYTES);
    cudaFuncSetAttribute(mm_fp16<false, true, false>,
                         cudaFuncAttributeMaxDynamicSharedMemorySize, SMEM_BYTES);

    const size_t sQKV = (size_t)SS * DD;
    const size_t sP   = (size_t)SS * SS;

    // 0) convert inputs to fp16
    cvtf2h_kernel<<<(BB * SS * DD) / 4 / 256, 256>>>(x,  X16);
    cvtf2h_kernel<<<(DD * DD) / 4 / 256, 256>>>(Wq, Wq16);
    cvtf2h_kernel<<<(DD * DD) / 4 / 256, 256>>>(Wk, Wk16);
    cvtf2h_kernel<<<(DD * DD) / 4 / 256, 256>>>(Wv, Wv16);

    // 1) QKV projections (fp16 out)
    dim3 gProj(DD / 128, (BB * SS) / 128, 1);
    mm_fp16<false, false, true><<<gProj, 256, SMEM_BYTES>>>(X16, Wq16, Q16, DD, DD, DD, DD, 0, 0, 0);
    mm_fp16<false, false, true><<<gProj, 256, SMEM_BYTES>>>(X16, Wk16, K16, DD, DD, DD, DD, 0, 0, 0);
    mm_fp16<false, false, true><<<gProj, 256, SMEM_BYTES>>>(X16, Wv16, V16, DD, DD, DD, DD, 0, 0, 0);

    // 2) V -> V^T (fp16)
    dim3 gT(DD / 32, SS / 32, BB);
    transpose16_kernel<<<gT, 256>>>(V16, VT16);

    // 3) Scores: P_b = Q_b @ K_b^T, fp32 out (skip strictly-upper tiles)
    dim3 gScore(SS / 128, SS / 128, BB);
    mm_fp16<true, false, false><<<gScore, 256, SMEM_BYTES>>>(Q16, K16, Pp, DD, DD, DD, SS,
                                                             sQKV, sQKV, sP);

    // 4) Causal softmax: fp32 scores -> fp16 probs
    softmax_causal_kernel<<<BB * SS, 256>>>(Pp, P16);

    // 5) O_b = P16_b @ (VT16_b)^T, fp32 out (K truncated by causality)
    dim3 gOut(DD / 128, SS / 128, BB);
    mm_fp16<false, true, false><<<gOut, 256, SMEM_BYTES>>>(P16, VT16, out, SS, SS, SS, DD,
                                                           sP, sQKV, sQKV);
}

// round 6
// speedup vs baseline: 7.2404x; 1.2322x over previous
#include <cuda_runtime.h>
#include <cuda_fp16.h>
#include <cstdint>
#include <cstddef>

#define BB 4
#define SS 2048
#define DD 1024

// Scratch (__device__ globals; allocation-free rule)
__device__ __half g_X16[BB * SS * DD];
__device__ __half g_Wq16[DD * DD];
__device__ __half g_Wk16[DD * DD];
__device__ __half g_Wv16[DD * DD];
__device__ __half g_Q16[BB * SS * DD];
__device__ __half g_K16[BB * SS * DD];
__device__ __half g_V16[BB * SS * DD];
__device__ __half g_VT16[BB * SS * DD];
__device__ __half g_P16[(size_t)BB * SS * SS];   // unnormalized exp scores
__device__ float  g_inv[BB * SS];                // 1 / rowsum

// exp2 factor: (1/sqrt(1024)) * log2(e)
#define EXPC 0.0450842200277801f

__device__ __forceinline__ uint32_t smem_u32(const void* p) {
    uint32_t a;
    asm("{ .reg .u64 t; cvta.to.shared.u64 t, %1; cvt.u32.u64 %0, t; }" : "=r"(a) : "l"(p));
    return a;
}
__device__ __forceinline__ void cp16(uint32_t dst, const void* src) {
    asm volatile("cp.async.cg.shared.global [%0], [%1], 16;" :: "r"(dst), "l"(src) : "memory");
}
__device__ __forceinline__ void ldsm_x4(uint32_t& r0, uint32_t& r1, uint32_t& r2,
                                        uint32_t& r3, uint32_t addr) {
    asm volatile("ldmatrix.sync.aligned.m8n8.x4.shared.b16 {%0,%1,%2,%3}, [%4];"
                 : "=r"(r0), "=r"(r1), "=r"(r2), "=r"(r3) : "r"(addr));
}
__device__ __forceinline__ void mma_fp16(float c[4], uint32_t a0, uint32_t a1,
                                         uint32_t a2, uint32_t a3,
                                         uint32_t b0, uint32_t b1) {
    asm volatile(
        "mma.sync.aligned.m16n8k16.row.col.f32.f16.f16.f32 "
        "{%0,%1,%2,%3}, {%4,%5,%6,%7}, {%8,%9}, {%0,%1,%2,%3};\n"
        : "+f"(c[0]), "+f"(c[1]), "+f"(c[2]), "+f"(c[3])
        : "r"(a0), "r"(a1), "r"(a2), "r"(a3), "r"(b0), "r"(b1));
}

// ===================== fp16 NT GEMM =====================
// C[m,n] = sum_k A[m,k]*B[n,k]; A:[M,K] rm fp16, B:[N,K] rm fp16.
// 128x128 CTA tile, BK=64, 256 thr (8 warps of 64x32), 3-stage cp.async ring,
// XOR-swizzled smem (128B rows, conflict-free ldmatrix), no padding.
// MODE 0: half out (projections)
// MODE 1: half out = exp2(v*EXPC) with causal mask (scores -> P~)
// MODE 2: float out scaled by Inv[row] (P~ . V -> O)
#define BK 64
#define OPB (128 * 128)               // bytes per operand tile
#define STG_BYTES (2 * OPB)           // 32768 per stage
#define STAGES 3
#define SMEM_BYTES (STAGES * STG_BYTES)

template<int MODE, bool SKIP_UPPER, bool KTRUNC>
__global__ void __launch_bounds__(256) mm_fp16(
    const __half* __restrict__ Ab, const __half* __restrict__ Bb, void* __restrict__ Cb,
    const float* __restrict__ Inv,
    int K, int lda, int ldb, int ldc, size_t sA, size_t sB, size_t sC)
{
    const int bx = blockIdx.x;
    const int by = KTRUNC ? (gridDim.y - 1 - blockIdx.y) : blockIdx.y;
    if (SKIP_UPPER && bx > by) return;

    extern __shared__ __align__(128) char smem[];
    const uint32_t sb = smem_u32(smem);

    const int tid  = threadIdx.x;
    const int wid  = tid >> 5, lane = tid & 31;
    const int wm   = wid & 1;            // warp row -> 64 rows
    const int wn   = wid >> 1;           // warp col -> 32 cols
    const int gid  = lane >> 2;
    const int tig  = lane & 3;

    const __half* A = Ab + blockIdx.z * sA + (size_t)by * 128 * lda;
    const __half* B = Bb + blockIdx.z * sB + (size_t)bx * 128 * ldb;

    const int kend = KTRUNC ? min(K, (by + 1) * 128) : K;
    const int NC   = kend / BK;          // >= 2 always

    // ldmatrix lane geometry (swizzled col16 index)
    const uint32_t swz    = lane & 7;
    const uint32_t rowA   = wm * 64 + (lane & 15);
    const uint32_t chalfA = lane >> 4;
    const uint32_t rowB   = wn * 32 + (lane & 7) + ((lane >> 4) << 3);
    const uint32_t chalfB = (lane >> 3) & 1;

    // cp.async: 8 segs/thread/operand; seg s -> row r = s>>3, col16 f = s&7
    auto issue_chunk = [&](int c) {
        const int stg = c - (c / 3) * 3;
        const uint32_t ab = sb + stg * STG_BYTES;
        const uint32_t bb = ab + OPB;
        const int k0 = c * BK;
        #pragma unroll
        for (int i = 0; i < 4; i++) {
            int s = tid + i * 256;
            uint32_t r = s >> 3, f = s & 7;
            uint32_t d = r * 128 + ((f ^ (r & 7)) << 4);
            cp16(ab + d, A + (size_t)r * lda + k0 + f * 8);
            cp16(bb + d, B + (size_t)r * ldb + k0 + f * 8);
        }
        asm volatile("cp.async.commit_group;" ::: "memory");
    };

    float acc[4][4][4];
    #pragma unroll
    for (int i = 0; i < 4; i++)
        #pragma unroll
        for (int j = 0; j < 4; j++)
            #pragma unroll
            for (int t = 0; t < 4; t++) acc[i][j][t] = 0.f;

    issue_chunk(0);
    issue_chunk(1);

    for (int c = 0; c < NC; c++) {
        asm volatile("cp.async.wait_group 1;" ::: "memory");   // chunk c arrived
        __syncthreads();
        if (c + 2 < NC) issue_chunk(c + 2);
        else asm volatile("cp.async.commit_group;" ::: "memory");

        const int stg = c - (c / 3) * 3;
        const uint32_t ab = sb + stg * STG_BYTES;
        const uint32_t bb = ab + OPB;

        #pragma unroll
        for (int ks = 0; ks < 4; ks++) {     // four k16 steps per BK=64
            uint32_t afr[4][4], bfr[2][4];
            #pragma unroll
            for (int mt = 0; mt < 4; mt++)
                ldsm_x4(afr[mt][0], afr[mt][1], afr[mt][2], afr[mt][3],
                        ab + (rowA + mt * 16) * 128
                           + ((((ks << 1) | chalfA) ^ swz) << 4));
            #pragma unroll
            for (int nt2 = 0; nt2 < 2; nt2++)
                ldsm_x4(bfr[nt2][0], bfr[nt2][1], bfr[nt2][2], bfr[nt2][3],
                        bb + (rowB + nt2 * 16) * 128
                           + ((((ks << 1) | chalfB) ^ swz) << 4));
            #pragma unroll
            for (int mt = 0; mt < 4; mt++)
                #pragma unroll
                for (int nt = 0; nt < 4; nt++)
                    mma_fp16(acc[mt][nt], afr[mt][0], afr[mt][1], afr[mt][2],
                             afr[mt][3], bfr[nt >> 1][(nt & 1) * 2],
                             bfr[nt >> 1][(nt & 1) * 2 + 1]);
        }
    }

    // Epilogue
    if (MODE == 0 || MODE == 1) {
        __half* C = (__half*)Cb + blockIdx.z * sC + (size_t)by * 128 * ldc
                  + (size_t)bx * 128;
        #pragma unroll
        for (int mt = 0; mt < 4; mt++) {
            int row0 = wm * 64 + mt * 16 + gid;
            #pragma unroll
            for (int nt = 0; nt < 4; nt++) {
                int col0 = wn * 32 + nt * 8 + tig * 2;
                float v0 = acc[mt][nt][0], v1 = acc[mt][nt][1];
                float v2 = acc[mt][nt][2], v3 = acc[mt][nt][3];
                if (MODE == 1) {
                    int grow0 = by * 128 + row0;        // q
                    int gcol0 = bx * 128 + col0;        // k
                    v0 = (gcol0     <= grow0)     ? exp2f(v0 * EXPC) : 0.f;
                    v1 = (gcol0 + 1 <= grow0)     ? exp2f(v1 * EXPC) : 0.f;
                    v2 = (gcol0     <= grow0 + 8) ? exp2f(v2 * EXPC) : 0.f;
                    v3 = (gcol0 + 1 <= grow0 + 8) ? exp2f(v3 * EXPC) : 0.f;
                }
                *(__half2*)(C + (size_t)row0       * ldc + col0) = __floats2half2_rn(v0, v1);
                *(__half2*)(C + (size_t)(row0 + 8) * ldc + col0) = __floats2half2_rn(v2, v3);
            }
        }
    } else {
        float* C = (float*)Cb + blockIdx.z * sC + (size_t)by * 128 * ldc
                 + (size_t)bx * 128;
        const float* InvB = Inv + blockIdx.z * SS;
        #pragma unroll
        for (int mt = 0; mt < 4; mt++) {
            int row0 = wm * 64 + mt * 16 + gid;
            float ia = InvB[by * 128 + row0];
            float ib = InvB[by * 128 + row0 + 8];
            #pragma unroll
            for (int nt = 0; nt < 4; nt++) {
                int col0 = wn * 32 + nt * 8 + tig * 2;
                *(float2*)(C + (size_t)row0       * ldc + col0) =
                    make_float2(acc[mt][nt][0] * ia, acc[mt][nt][1] * ia);
                *(float2*)(C + (size_t)(row0 + 8) * ldc + col0) =
                    make_float2(acc[mt][nt][2] * ib, acc[mt][nt][3] * ib);
            }
        }
    }
}

// ===================== fp32 -> fp16 convert ==================================
__global__ void __launch_bounds__(256) cvtf2h_kernel(
    const float* __restrict__ in, __half* __restrict__ out)
{
    size_t i = (size_t)blockIdx.x * 256 + threadIdx.x;
    float4 v = ((const float4*)in)[i];
    ((__half2*)out)[i * 2]     = __floats2half2_rn(v.x, v.y);
    ((__half2*)out)[i * 2 + 1] = __floats2half2_rn(v.z, v.w);
}

// ===================== V16 -> V16^T transpose (per batch) ====================
__global__ void __launch_bounds__(256) transpose16_kernel(
    const __half* __restrict__ V, __half* __restrict__ VT)
{
    __shared__ __half t[32][34];
    int z = blockIdx.z;
    const __half* Vb = V + (size_t)z * SS * DD;
    __half* VTb = VT + (size_t)z * SS * DD;
    int d0 = blockIdx.x * 32, s0 = blockIdx.y * 32;
    int tx = threadIdx.x & 31, ty = threadIdx.x >> 5;   // 32 x 8
    #pragma unroll
    for (int j = 0; j < 4; j++)
        t[ty + j * 8][tx] = Vb[(size_t)(s0 + ty + j * 8) * DD + d0 + tx];
    __syncthreads();
    #pragma unroll
    for (int j = 0; j < 4; j++)
        VTb[(size_t)(d0 + ty + j * 8) * SS + s0 + tx] = t[tx][ty + j * 8];
}

// ===================== rowsum of P~ -> inverse ===============================
// One warp per row; only the written region [0, (q/128+1)*128) is touched.
__global__ void __launch_bounds__(256) rowsum_kernel(
    const __half* __restrict__ P16, float* __restrict__ inv)
{
    int row  = blockIdx.x * 8 + (threadIdx.x >> 5);   // 0 .. B*S-1
    int lane = threadIdx.x & 31;
    const __half2* p = (const __half2*)(P16 + (size_t)row * SS);
    int q  = row & (SS - 1);
    int n2 = (((q >> 7) + 1) << 7) >> 1;              // half2 count, mult of 64
    float s = 0.f;
    for (int i = lane; i < n2; i += 32) {
        float2 v = __half22float2(p[i]);
        s += v.x + v.y;
    }
    #pragma unroll
    for (int o = 16; o; o >>= 1) s += __shfl_xor_sync(0xFFFFFFFFu, s, o);
    if (lane == 0) inv[row] = 1.0f / s;
}

// ===========================================================================
extern "C" void kernel_launch(void* const* d_in, const int* in_sizes, int n_in,
                              void* d_out, int out_size)
{
    const float* x  = (const float*)d_in[0];
    const float* Wq = (const float*)d_in[1];
    const float* Wk = (const float*)d_in[2];
    const float* Wv = (const float*)d_in[3];
    float* out = (float*)d_out;

    __half *X16, *Wq16, *Wk16, *Wv16, *Q16, *K16, *V16, *VT16, *P16;
    float *invp;
    cudaGetSymbolAddress((void**)&X16,  g_X16);
    cudaGetSymbolAddress((void**)&Wq16, g_Wq16);
    cudaGetSymbolAddress((void**)&Wk16, g_Wk16);
    cudaGetSymbolAddress((void**)&Wv16, g_Wv16);
    cudaGetSymbolAddress((void**)&Q16,  g_Q16);
    cudaGetSymbolAddress((void**)&K16,  g_K16);
    cudaGetSymbolAddress((void**)&V16,  g_V16);
    cudaGetSymbolAddress((void**)&VT16, g_VT16);
    cudaGetSymbolAddress((void**)&P16,  g_P16);
    cudaGetSymbolAddress((void**)&invp, g_inv);

    cudaFuncSetAttribute(mm_fp16<0, false, false>,
                         cudaFuncAttributeMaxDynamicSharedMemorySize, SMEM_BYTES);
    cudaFuncSetAttribute(mm_fp16<1, true, false>,
                         cudaFuncAttributeMaxDynamicSharedMemorySize, SMEM_BYTES);
    cudaFuncSetAttribute(mm_fp16<2, false, true>,
                         cudaFuncAttributeMaxDynamicSharedMemorySize, SMEM_BYTES);

    const size_t sQKV = (size_t)SS * DD;
    const size_t sP   = (size_t)SS * SS;

    // 0) convert inputs to fp16
    cvtf2h_kernel<<<(BB * SS * DD) / 4 / 256, 256>>>(x,  X16);
    cvtf2h_kernel<<<(DD * DD) / 4 / 256, 256>>>(Wq, Wq16);
    cvtf2h_kernel<<<(DD * DD) / 4 / 256, 256>>>(Wk, Wk16);
    cvtf2h_kernel<<<(DD * DD) / 4 / 256, 256>>>(Wv, Wv16);

    // 1) QKV projections (fp16 out)
    dim3 gProj(DD / 128, (BB * SS) / 128, 1);
    mm_fp16<0, false, false><<<gProj, 256, SMEM_BYTES>>>(X16, Wq16, Q16, nullptr,
                                                         DD, DD, DD, DD, 0, 0, 0);
    mm_fp16<0, false, false><<<gProj, 256, SMEM_BYTES>>>(X16, Wk16, K16, nullptr,
                                                         DD, DD, DD, DD, 0, 0, 0);
    mm_fp16<0, false, false><<<gProj, 256, SMEM_BYTES>>>(X16, Wv16, V16, nullptr,
                                                         DD, DD, DD, DD, 0, 0, 0);

    // 2) V -> V^T (fp16)
    dim3 gT(DD / 32, SS / 32, BB);
    transpose16_kernel<<<gT, 256>>>(V16, VT16);

    // 3) Scores + exp + causal mask: P~_b = exp(Q_b K_b^T / 32), fp16 out
    dim3 gScore(SS / 128, SS / 128, BB);
    mm_fp16<1, true, false><<<gScore, 256, SMEM_BYTES>>>(Q16, K16, P16, nullptr,
                                                         DD, DD, DD, SS,
                                                         sQKV, sQKV, sP);

    // 4) Row sums -> inverses
    rowsum_kernel<<<BB * SS / 8, 256>>>(P16, invp);

    // 5) O_b = diag(inv) * (P~_b @ V_b)   (K truncated; heavy tiles first)
    dim3 gOut(DD / 128, SS / 128, BB);
    mm_fp16<2, false, true><<<gOut, 256, SMEM_BYTES>>>(P16, VT16, out, invp,
                                                       SS, SS, SS, DD,
                                                       sP, sQKV, sQKV);
}

// round 7
// speedup vs baseline: 7.8361x; 1.0823x over previous
#include <cuda_runtime.h>
#include <cuda_fp16.h>
#include <cstdint>
#include <cstddef>

#define BB 4
#define SS 2048
#define DD 1024
#define ND3 (3 * DD)    // packed QKV width = 3072

// Scratch (__device__ globals; allocation-free rule)
__device__ __half g_X16[BB * SS * DD];
__device__ __half g_Wcat16[ND3 * DD];              // [Wq; Wk; Wv] rows
__device__ __half g_QKV16[(size_t)BB * SS * ND3];  // [B*S, 3072]: Q|K|V
__device__ __half g_VT16[BB * SS * DD];            // per batch [D, S]
__device__ __half g_P16[(size_t)BB * SS * SS];     // unnormalized exp scores
__device__ float  g_inv[BB * SS];                  // 1 / rowsum

// exp2 factor: (1/sqrt(1024)) * log2(e)
#define EXPC 0.0450842200277801f

__device__ __forceinline__ uint32_t smem_u32(const void* p) {
    uint32_t a;
    asm("{ .reg .u64 t; cvta.to.shared.u64 t, %1; cvt.u32.u64 %0, t; }" : "=r"(a) : "l"(p));
    return a;
}
__device__ __forceinline__ void cp16(uint32_t dst, const void* src) {
    asm volatile("cp.async.cg.shared.global [%0], [%1], 16;" :: "r"(dst), "l"(src) : "memory");
}
__device__ __forceinline__ void ldsm_x4(uint32_t& r0, uint32_t& r1, uint32_t& r2,
                                        uint32_t& r3, uint32_t addr) {
    asm volatile("ldmatrix.sync.aligned.m8n8.x4.shared.b16 {%0,%1,%2,%3}, [%4];"
                 : "=r"(r0), "=r"(r1), "=r"(r2), "=r"(r3) : "r"(addr));
}
__device__ __forceinline__ void mma_fp16(float c[4], uint32_t a0, uint32_t a1,
                                         uint32_t a2, uint32_t a3,
                                         uint32_t b0, uint32_t b1) {
    asm volatile(
        "mma.sync.aligned.m16n8k16.row.col.f32.f16.f16.f32 "
        "{%0,%1,%2,%3}, {%4,%5,%6,%7}, {%8,%9}, {%0,%1,%2,%3};\n"
        : "+f"(c[0]), "+f"(c[1]), "+f"(c[2]), "+f"(c[3])
        : "r"(a0), "r"(a1), "r"(a2), "r"(a3), "r"(b0), "r"(b1));
}

// ===================== fp16 NT GEMM =====================
// C[m,n] = sum_k A[m,k]*B[n,k]; A:[M,K] rm fp16, B:[N,K] rm fp16.
// CTA tile 128 x (NFRAG*32), BK=64, 256 thr (8 warps, 2x4 of 64x(NFRAG*8)),
// 3-stage cp.async ring, XOR-swizzled smem (128B rows), conflict-free ldmatrix.
// MODE 0: half out (projections)
// MODE 1: half out = exp2(v*EXPC) + causal mask; triangular-packed grid.x
// MODE 2: float out scaled by Inv[row] (P~ . V -> O)
#define BK 64
#define OPB (128 * 128)               // bytes per operand region (B padded to 128 rows)
#define STG_BYTES (2 * OPB)           // 32768 per stage
#define STAGES 3
#define SMEM_BYTES (STAGES * STG_BYTES)

template<int MODE, int NFRAG, bool KTRUNC>
__global__ void __launch_bounds__(256) mm_fp16(
    const __half* __restrict__ Ab, const __half* __restrict__ Bb, void* __restrict__ Cb,
    const float* __restrict__ Inv,
    int K, int lda, int ldb, int ldc, size_t sA, size_t sB, size_t sC)
{
    constexpr int NTILE = NFRAG * 32;     // CTA n extent
    constexpr int WN    = NFRAG * 8;      // per-warp n extent

    int bx, by;
    if (MODE == 1) {            // triangular-packed: blockIdx.x -> (bx <= by)
        int t = blockIdx.x;
        by = (int)((sqrtf(8.f * (float)t + 1.f) - 1.f) * 0.5f);
        while ((by + 1) * (by + 2) / 2 <= t) by++;
        while (by * (by + 1) / 2 > t)       by--;
        bx = t - by * (by + 1) / 2;
    } else {
        bx = blockIdx.x;
        by = KTRUNC ? (gridDim.y - 1 - blockIdx.y) : blockIdx.y;
    }

    extern __shared__ __align__(128) char smem[];
    const uint32_t sb = smem_u32(smem);

    const int tid  = threadIdx.x;
    const int wid  = tid >> 5, lane = tid & 31;
    const int wm   = wid & 1;            // warp row -> 64 rows
    const int wn   = wid >> 1;           // warp col -> WN cols
    const int gid  = lane >> 2;
    const int tig  = lane & 3;

    const __half* A = Ab + blockIdx.z * sA + (size_t)by * 128 * lda;
    const __half* B = Bb + blockIdx.z * sB + (size_t)bx * NTILE * ldb;

    const int kend = KTRUNC ? min(K, (by + 1) * 128) : K;
    const int NC   = kend / BK;          // >= 2 always

    // ldmatrix lane geometry (swizzled col16 index)
    const uint32_t swz    = lane & 7;
    const uint32_t rowA   = wm * 64 + (lane & 15);
    const uint32_t chalfA = lane >> 4;
    const uint32_t rowB   = wn * WN + (lane & 7) + ((lane >> 4) << 3);
    const uint32_t chalfB = (lane >> 3) & 1;

    // cp.async: A 128 rows (4 segs/thr), B NTILE rows (NFRAG segs/thr)
    auto issue_chunk = [&](int c) {
        const int stg = c - (c / 3) * 3;
        const uint32_t ab = sb + stg * STG_BYTES;
        const uint32_t bb = ab + OPB;
        const int k0 = c * BK;
        #pragma unroll
        for (int i = 0; i < 4; i++) {
            int s = tid + i * 256;
            uint32_t r = s >> 3, f = s & 7;
            uint32_t d = r * 128 + ((f ^ (r & 7)) << 4);
            cp16(ab + d, A + (size_t)r * lda + k0 + f * 8);
        }
        #pragma unroll
        for (int i = 0; i < NFRAG; i++) {
            int s = tid + i * 256;
            uint32_t r = s >> 3, f = s & 7;
            uint32_t d = r * 128 + ((f ^ (r & 7)) << 4);
            cp16(bb + d, B + (size_t)r * ldb + k0 + f * 8);
        }
        asm volatile("cp.async.commit_group;" ::: "memory");
    };

    float acc[4][NFRAG][4];
    #pragma unroll
    for (int i = 0; i < 4; i++)
        #pragma unroll
        for (int j = 0; j < NFRAG; j++)
            #pragma unroll
            for (int t = 0; t < 4; t++) acc[i][j][t] = 0.f;

    issue_chunk(0);
    issue_chunk(1);

    for (int c = 0; c < NC; c++) {
        asm volatile("cp.async.wait_group 1;" ::: "memory");   // chunk c arrived
        __syncthreads();
        if (c + 2 < NC) issue_chunk(c + 2);
        else asm volatile("cp.async.commit_group;" ::: "memory");

        const int stg = c - (c / 3) * 3;
        const uint32_t ab = sb + stg * STG_BYTES;
        const uint32_t bb = ab + OPB;

        #pragma unroll
        for (int ks = 0; ks < 4; ks++) {     // four k16 steps per BK=64
            uint32_t afr[4][4], bfr[2][4];
            #pragma unroll
            for (int mt = 0; mt < 4; mt++)
                ldsm_x4(afr[mt][0], afr[mt][1], afr[mt][2], afr[mt][3],
                        ab + (rowA + mt * 16) * 128
                           + ((((ks << 1) | chalfA) ^ swz) << 4));
            #pragma unroll
            for (int nt2 = 0; nt2 < 2; nt2++)
                ldsm_x4(bfr[nt2][0], bfr[nt2][1], bfr[nt2][2], bfr[nt2][3],
                        bb + (rowB + nt2 * 16) * 128
                           + ((((ks << 1) | chalfB) ^ swz) << 4));
            #pragma unroll
            for (int mt = 0; mt < 4; mt++)
                #pragma unroll
                for (int nt = 0; nt < NFRAG; nt++)
                    mma_fp16(acc[mt][nt], afr[mt][0], afr[mt][1], afr[mt][2],
                             afr[mt][3], bfr[nt >> 1][(nt & 1) * 2],
                             bfr[nt >> 1][(nt & 1) * 2 + 1]);
        }
    }

    // Epilogue
    if (MODE == 0 || MODE == 1) {
        __half* C = (__half*)Cb + blockIdx.z * sC + (size_t)by * 128 * ldc
                  + (size_t)bx * NTILE;
        #pragma unroll
        for (int mt = 0; mt < 4; mt++) {
            int row0 = wm * 64 + mt * 16 + gid;
            #pragma unroll
            for (int nt = 0; nt < NFRAG; nt++) {
                int col0 = wn * WN + nt * 8 + tig * 2;
                float v0 = acc[mt][nt][0], v1 = acc[mt][nt][1];
                float v2 = acc[mt][nt][2], v3 = acc[mt][nt][3];
                if (MODE == 1) {
                    int grow0 = by * 128 + row0;        // q
                    int gcol0 = bx * NTILE + col0;      // k
                    v0 = (gcol0     <= grow0)     ? exp2f(v0 * EXPC) : 0.f;
                    v1 = (gcol0 + 1 <= grow0)     ? exp2f(v1 * EXPC) : 0.f;
                    v2 = (gcol0     <= grow0 + 8) ? exp2f(v2 * EXPC) : 0.f;
                    v3 = (gcol0 + 1 <= grow0 + 8) ? exp2f(v3 * EXPC) : 0.f;
                }
                *(__half2*)(C + (size_t)row0       * ldc + col0) = __floats2half2_rn(v0, v1);
                *(__half2*)(C + (size_t)(row0 + 8) * ldc + col0) = __floats2half2_rn(v2, v3);
            }
        }
    } else {
        float* C = (float*)Cb + blockIdx.z * sC + (size_t)by * 128 * ldc
                 + (size_t)bx * NTILE;
        const float* InvB = Inv + blockIdx.z * SS;
        #pragma unroll
        for (int mt = 0; mt < 4; mt++) {
            int row0 = wm * 64 + mt * 16 + gid;
            float ia = InvB[by * 128 + row0];
            float ib = InvB[by * 128 + row0 + 8];
            #pragma unroll
            for (int nt = 0; nt < NFRAG; nt++) {
                int col0 = wn * WN + nt * 8 + tig * 2;
                *(float2*)(C + (size_t)row0       * ldc + col0) =
                    make_float2(acc[mt][nt][0] * ia, acc[mt][nt][1] * ia);
                *(float2*)(C + (size_t)(row0 + 8) * ldc + col0) =
                    make_float2(acc[mt][nt][2] * ib, acc[mt][nt][3] * ib);
            }
        }
    }
}

// ===================== fp32 -> fp16 convert ==================================
__global__ void __launch_bounds__(256) cvtf2h_kernel(
    const float* __restrict__ in, __half* __restrict__ out)
{
    size_t i = (size_t)blockIdx.x * 256 + threadIdx.x;
    float4 v = ((const float4*)in)[i];
    ((__half2*)out)[i * 2]     = __floats2half2_rn(v.x, v.y);
    ((__half2*)out)[i * 2 + 1] = __floats2half2_rn(v.z, v.w);
}

// ===================== V (cols 2048.. of QKV) -> V^T (per batch) =============
__global__ void __launch_bounds__(256) transpose16_kernel(
    const __half* __restrict__ QKV, __half* __restrict__ VT)
{
    __shared__ __half t[32][34];
    int z = blockIdx.z;
    const __half* Vb = QKV + (size_t)z * SS * ND3 + 2 * DD;
    __half* VTb = VT + (size_t)z * SS * DD;
    int d0 = blockIdx.x * 32, s0 = blockIdx.y * 32;
    int tx = threadIdx.x & 31, ty = threadIdx.x >> 5;   // 32 x 8
    #pragma unroll
    for (int j = 0; j < 4; j++)
        t[ty + j * 8][tx] = Vb[(size_t)(s0 + ty + j * 8) * ND3 + d0 + tx];
    __syncthreads();
    #pragma unroll
    for (int j = 0; j < 4; j++)
        VTb[(size_t)(d0 + ty + j * 8) * SS + s0 + tx] = t[tx][ty + j * 8];
}

// ===================== rowsum of P~ -> inverse ===============================
__global__ void __launch_bounds__(256) rowsum_kernel(
    const __half* __restrict__ P16, float* __restrict__ inv)
{
    int row  = blockIdx.x * 8 + (threadIdx.x >> 5);   // 0 .. B*S-1
    int lane = threadIdx.x & 31;
    const __half2* p = (const __half2*)(P16 + (size_t)row * SS);
    int q  = row & (SS - 1);
    int n2 = (((q >> 7) + 1) << 7) >> 1;              // half2 count, mult of 64
    float s = 0.f;
    for (int i = lane; i < n2; i += 32) {
        float2 v = __half22float2(p[i]);
        s += v.x + v.y;
    }
    #pragma unroll
    for (int o = 16; o; o >>= 1) s += __shfl_xor_sync(0xFFFFFFFFu, s, o);
    if (lane == 0) inv[row] = 1.0f / s;
}

// ===========================================================================
extern "C" void kernel_launch(void* const* d_in, const int* in_sizes, int n_in,
                              void* d_out, int out_size)
{
    const float* x  = (const float*)d_in[0];
    const float* Wq = (const float*)d_in[1];
    const float* Wk = (const float*)d_in[2];
    const float* Wv = (const float*)d_in[3];
    float* out = (float*)d_out;

    __half *X16, *Wcat, *QKV, *VT16, *P16;
    float *invp;
    cudaGetSymbolAddress((void**)&X16,  g_X16);
    cudaGetSymbolAddress((void**)&Wcat, g_Wcat16);
    cudaGetSymbolAddress((void**)&QKV,  g_QKV16);
    cudaGetSymbolAddress((void**)&VT16, g_VT16);
    cudaGetSymbolAddress((void**)&P16,  g_P16);
    cudaGetSymbolAddress((void**)&invp, g_inv);

    cudaFuncSetAttribute(mm_fp16<0, 3, false>,
                         cudaFuncAttributeMaxDynamicSharedMemorySize, SMEM_BYTES);
    cudaFuncSetAttribute(mm_fp16<1, 4, false>,
                         cudaFuncAttributeMaxDynamicSharedMemorySize, SMEM_BYTES);
    cudaFuncSetAttribute(mm_fp16<2, 4, true>,
                         cudaFuncAttributeMaxDynamicSharedMemorySize, SMEM_BYTES);

    const size_t sQKV3 = (size_t)SS * ND3;   // per-batch stride in packed QKV
    const size_t sV    = (size_t)SS * DD;
    const size_t sP    = (size_t)SS * SS;

    // 0) convert inputs to fp16 (weights packed into one [3072, 1024] buffer)
    cvtf2h_kernel<<<(BB * SS * DD) / 4 / 256, 256>>>(x,  X16);
    cvtf2h_kernel<<<(DD * DD) / 4 / 256, 256>>>(Wq, Wcat);
    cvtf2h_kernel<<<(DD * DD) / 4 / 256, 256>>>(Wk, Wcat + DD * DD);
    cvtf2h_kernel<<<(DD * DD) / 4 / 256, 256>>>(Wv, Wcat + 2 * DD * DD);

    // 1) Fused QKV projection: [8192, 3072] = X @ Wcat^T, N-tile=96
    dim3 gProj(ND3 / 96, (BB * SS) / 128, 1);
    mm_fp16<0, 3, false><<<gProj, 256, SMEM_BYTES>>>(X16, Wcat, QKV, nullptr,
                                                     DD, DD, DD, ND3, 0, 0, 0);

    // 2) V -> V^T (fp16)
    dim3 gT(DD / 32, SS / 32, BB);
    transpose16_kernel<<<gT, 256>>>(QKV, VT16);

    // 3) Scores + exp + mask: P~ = exp(Q K^T / 32); triangular-packed grid
    const int TTILES = (SS / 128) * (SS / 128 + 1) / 2;   // 136
    dim3 gScore(TTILES, 1, BB);
    mm_fp16<1, 4, false><<<gScore, 256, SMEM_BYTES>>>(QKV, QKV + DD, P16, nullptr,
                                                      DD, ND3, ND3, SS,
                                                      sQKV3, sQKV3, sP);

    // 4) Row sums -> inverses
    rowsum_kernel<<<BB * SS / 8, 256>>>(P16, invp);

    // 5) O = diag(inv) * (P~ @ V)   (K truncated; heavy tiles first)
    dim3 gOut(DD / 128, SS / 128, BB);
    mm_fp16<2, 4, true><<<gOut, 256, SMEM_BYTES>>>(P16, VT16, out, invp,
                                                   SS, SS, SS, DD,
                                                   sP, sV, sV);
}

// round 8
// speedup vs baseline: 8.0397x; 1.0260x over previous
#include <cuda_runtime.h>
#include <cuda_fp16.h>
#include <cstdint>
#include <cstddef>

#define BB 4
#define SS 2048
#define DD 1024
#define ND3 (3 * DD)    // packed QKV width = 3072

// Scratch (__device__ globals; allocation-free rule)
__device__ __half g_X16[BB * SS * DD];
__device__ __half g_Wcat16[ND3 * DD];              // [Wq; Wk; Wv] rows
__device__ __half g_QKV16[(size_t)BB * SS * ND3];  // [B*S, 3072]: Q|K|V
__device__ __half g_VT16[BB * SS * DD];            // per batch [D, S]
__device__ __half g_P16[(size_t)BB * SS * SS];     // unnormalized exp scores
__device__ float  g_rs[BB * SS * 16];              // per-(row, bxTile) partial sums

// exp2 factor: (1/sqrt(1024)) * log2(e)
#define EXPC 0.0450842200277801f

__device__ __forceinline__ uint32_t smem_u32(const void* p) {
    uint32_t a;
    asm("{ .reg .u64 t; cvta.to.shared.u64 t, %1; cvt.u32.u64 %0, t; }" : "=r"(a) : "l"(p));
    return a;
}
__device__ __forceinline__ void cp16(uint32_t dst, const void* src) {
    asm volatile("cp.async.cg.shared.global [%0], [%1], 16;" :: "r"(dst), "l"(src) : "memory");
}
__device__ __forceinline__ void ldsm_x4(uint32_t& r0, uint32_t& r1, uint32_t& r2,
                                        uint32_t& r3, uint32_t addr) {
    asm volatile("ldmatrix.sync.aligned.m8n8.x4.shared.b16 {%0,%1,%2,%3}, [%4];"
                 : "=r"(r0), "=r"(r1), "=r"(r2), "=r"(r3) : "r"(addr));
}
__device__ __forceinline__ void mma_fp16(float c[4], uint32_t a0, uint32_t a1,
                                         uint32_t a2, uint32_t a3,
                                         uint32_t b0, uint32_t b1) {
    asm volatile(
        "mma.sync.aligned.m16n8k16.row.col.f32.f16.f16.f32 "
        "{%0,%1,%2,%3}, {%4,%5,%6,%7}, {%8,%9}, {%0,%1,%2,%3};\n"
        : "+f"(c[0]), "+f"(c[1]), "+f"(c[2]), "+f"(c[3])
        : "r"(a0), "r"(a1), "r"(a2), "r"(a3), "r"(b0), "r"(b1));
}

// ===================== fp16 NT GEMM =====================
// C[m,n] = sum_k A[m,k]*B[n,k]; A:[M,K] rm fp16, B:[N,K] rm fp16.
// CTA tile 128 x (NFRAG*32), BK=64, 256 thr, 3-stage cp.async ring,
// XOR-swizzled smem (128B rows), conflict-free ldmatrix.
// MODE 0: half out (projection)
// MODE 1: half out = exp2(v*EXPC) + causal mask; triangular grid;
//         emits per-row partial sums into g_rs[b][row][bx]
// MODE 2: float out scaled by 1/rowsum (computed from g_rs in prologue)
#define BK 64
#define OPB (128 * 128)               // bytes per operand region
#define STG_BYTES (2 * OPB)           // 32768 per stage
#define STAGES 3
#define SMEM_BYTES (STAGES * STG_BYTES + 512)
#define INV_OFF (STAGES * STG_BYTES)

template<int MODE, int NFRAG, bool KTRUNC>
__global__ void __launch_bounds__(256) mm_fp16(
    const __half* __restrict__ Ab, const __half* __restrict__ Bb, void* __restrict__ Cb,
    const float* __restrict__ Rs, float* __restrict__ RsOut,
    int K, int lda, int ldb, int ldc, size_t sA, size_t sB, size_t sC)
{
    constexpr int NTILE = NFRAG * 32;     // CTA n extent
    constexpr int WN    = NFRAG * 8;      // per-warp n extent

    int bx, by;
    if (MODE == 1) {            // triangular-packed: blockIdx.x -> (bx <= by)
        int t = blockIdx.x;
        by = (int)((sqrtf(8.f * (float)t + 1.f) - 1.f) * 0.5f);
        while ((by + 1) * (by + 2) / 2 <= t) by++;
        while (by * (by + 1) / 2 > t)       by--;
        bx = t - by * (by + 1) / 2;
    } else {
        bx = blockIdx.x;
        by = KTRUNC ? (gridDim.y - 1 - blockIdx.y) : blockIdx.y;
    }

    extern __shared__ __align__(128) char smem[];
    const uint32_t sb = smem_u32(smem);

    const int tid  = threadIdx.x;
    const int wid  = tid >> 5, lane = tid & 31;
    const int wm   = wid & 1;            // warp row -> 64 rows
    const int wn   = wid >> 1;           // warp col -> WN cols
    const int gid  = lane >> 2;
    const int tig  = lane & 3;

    const __half* A = Ab + blockIdx.z * sA + (size_t)by * 128 * lda;
    const __half* B = Bb + blockIdx.z * sB + (size_t)bx * NTILE * ldb;

    const int kend = KTRUNC ? min(K, (by + 1) * 128) : K;
    const int NC   = kend / BK;          // >= 2 always

    // ldmatrix lane geometry (swizzled col16 index)
    const uint32_t swz    = lane & 7;
    const uint32_t rowA   = wm * 64 + (lane & 15);
    const uint32_t chalfA = lane >> 4;
    const uint32_t rowB   = wn * WN + (lane & 7) + ((lane >> 4) << 3);
    const uint32_t chalfB = (lane >> 3) & 1;

    auto issue_chunk = [&](int c) {
        const int stg = c - (c / 3) * 3;
        const uint32_t ab = sb + stg * STG_BYTES;
        const uint32_t bb = ab + OPB;
        const int k0 = c * BK;
        #pragma unroll
        for (int i = 0; i < 4; i++) {
            int s = tid + i * 256;
            uint32_t r = s >> 3, f = s & 7;
            uint32_t d = r * 128 + ((f ^ (r & 7)) << 4);
            cp16(ab + d, A + (size_t)r * lda + k0 + f * 8);
        }
        #pragma unroll
        for (int i = 0; i < NFRAG; i++) {
            int s = tid + i * 256;
            uint32_t r = s >> 3, f = s & 7;
            uint32_t d = r * 128 + ((f ^ (r & 7)) << 4);
            cp16(bb + d, B + (size_t)r * ldb + k0 + f * 8);
        }
        asm volatile("cp.async.commit_group;" ::: "memory");
    };

    float acc[4][NFRAG][4];
    #pragma unroll
    for (int i = 0; i < 4; i++)
        #pragma unroll
        for (int j = 0; j < NFRAG; j++)
            #pragma unroll
            for (int t = 0; t < 4; t++) acc[i][j][t] = 0.f;

    issue_chunk(0);
    issue_chunk(1);

    // MODE 2 prologue: compute 1/rowsum for this CTA's 128 rows from partials.
    if (MODE == 2 && tid < 128) {
        const float* rs = Rs + ((size_t)blockIdx.z * SS + by * 128 + tid) * 16;
        float s = 0.f;
        for (int j = 0; j <= by; j++) s += rs[j];
        ((float*)(smem + INV_OFF))[tid] = 1.0f / s;
    }

    for (int c = 0; c < NC; c++) {
        asm volatile("cp.async.wait_group 1;" ::: "memory");   // chunk c arrived
        __syncthreads();
        if (c + 2 < NC) issue_chunk(c + 2);
        else asm volatile("cp.async.commit_group;" ::: "memory");

        const int stg = c - (c / 3) * 3;
        const uint32_t ab = sb + stg * STG_BYTES;
        const uint32_t bb = ab + OPB;

        #pragma unroll
        for (int ks = 0; ks < 4; ks++) {     // four k16 steps per BK=64
            uint32_t afr[4][4], bfr[2][4];
            #pragma unroll
            for (int mt = 0; mt < 4; mt++)
                ldsm_x4(afr[mt][0], afr[mt][1], afr[mt][2], afr[mt][3],
                        ab + (rowA + mt * 16) * 128
                           + ((((ks << 1) | chalfA) ^ swz) << 4));
            #pragma unroll
            for (int nt2 = 0; nt2 < 2; nt2++)
                ldsm_x4(bfr[nt2][0], bfr[nt2][1], bfr[nt2][2], bfr[nt2][3],
                        bb + (rowB + nt2 * 16) * 128
                           + ((((ks << 1) | chalfB) ^ swz) << 4));
            #pragma unroll
            for (int mt = 0; mt < 4; mt++)
                #pragma unroll
                for (int nt = 0; nt < NFRAG; nt++)
                    mma_fp16(acc[mt][nt], afr[mt][0], afr[mt][1], afr[mt][2],
                             afr[mt][3], bfr[nt >> 1][(nt & 1) * 2],
                             bfr[nt >> 1][(nt & 1) * 2 + 1]);
        }
    }

    // Epilogue
    if (MODE == 0) {
        __half* C = (__half*)Cb + blockIdx.z * sC + (size_t)by * 128 * ldc
                  + (size_t)bx * NTILE;
        #pragma unroll
        for (int mt = 0; mt < 4; mt++) {
            int row0 = wm * 64 + mt * 16 + gid;
            #pragma unroll
            for (int nt = 0; nt < NFRAG; nt++) {
                int col0 = wn * WN + nt * 8 + tig * 2;
                *(__half2*)(C + (size_t)row0       * ldc + col0) =
                    __floats2half2_rn(acc[mt][nt][0], acc[mt][nt][1]);
                *(__half2*)(C + (size_t)(row0 + 8) * ldc + col0) =
                    __floats2half2_rn(acc[mt][nt][2], acc[mt][nt][3]);
            }
        }
    } else if (MODE == 1) {
        __half* C = (__half*)Cb + blockIdx.z * sC + (size_t)by * 128 * ldc
                  + (size_t)bx * NTILE;
        float srow[4][2];                       // per-thread row partials per mt
        #pragma unroll
        for (int mt = 0; mt < 4; mt++) { srow[mt][0] = 0.f; srow[mt][1] = 0.f; }

        #pragma unroll
        for (int mt = 0; mt < 4; mt++) {
            int row0 = wm * 64 + mt * 16 + gid;
            int grow0 = by * 128 + row0;        // q
            #pragma unroll
            for (int nt = 0; nt < NFRAG; nt++) {
                int col0 = wn * WN + nt * 8 + tig * 2;
                int gcol0 = bx * NTILE + col0;  // k
                float v0 = (gcol0     <= grow0)     ? exp2f(acc[mt][nt][0] * EXPC) : 0.f;
                float v1 = (gcol0 + 1 <= grow0)     ? exp2f(acc[mt][nt][1] * EXPC) : 0.f;
                float v2 = (gcol0     <= grow0 + 8) ? exp2f(acc[mt][nt][2] * EXPC) : 0.f;
                float v3 = (gcol0 + 1 <= grow0 + 8) ? exp2f(acc[mt][nt][3] * EXPC) : 0.f;
                srow[mt][0] += v0 + v1;
                srow[mt][1] += v2 + v3;
                *(__half2*)(C + (size_t)row0       * ldc + col0) = __floats2half2_rn(v0, v1);
                *(__half2*)(C + (size_t)(row0 + 8) * ldc + col0) = __floats2half2_rn(v2, v3);
            }
        }
        // reduce across the 4 tig lanes of each row group
        #pragma unroll
        for (int mt = 0; mt < 4; mt++) {
            #pragma unroll
            for (int h = 0; h < 2; h++) {
                float s = srow[mt][h];
                s += __shfl_xor_sync(0xFFFFFFFFu, s, 1);
                s += __shfl_xor_sync(0xFFFFFFFFu, s, 2);
                srow[mt][h] = s;
            }
        }
        __syncthreads();                        // pipeline smem no longer needed
        float* part = (float*)smem;             // [128][4]
        if (tig == 0) {
            #pragma unroll
            for (int mt = 0; mt < 4; mt++) {
                int rl = wm * 64 + mt * 16 + gid;
                part[rl * 4 + wn]       = srow[mt][0];
                part[(rl + 8) * 4 + wn] = srow[mt][1];
            }
        }
        __syncthreads();
        if (tid < 128) {
            float s = part[tid * 4] + part[tid * 4 + 1]
                    + part[tid * 4 + 2] + part[tid * 4 + 3];
            RsOut[((size_t)blockIdx.z * SS + by * 128 + tid) * 16 + bx] = s;
        }
    } else {
        float* C = (float*)Cb + blockIdx.z * sC + (size_t)by * 128 * ldc
                 + (size_t)bx * NTILE;
        const float* invs = (const float*)(smem + INV_OFF);
        #pragma unroll
        for (int mt = 0; mt < 4; mt++) {
            int row0 = wm * 64 + mt * 16 + gid;
            float ia = invs[row0];
            float ib = invs[row0 + 8];
            #pragma unroll
            for (int nt = 0; nt < NFRAG; nt++) {
                int col0 = wn * WN + nt * 8 + tig * 2;
                *(float2*)(C + (size_t)row0       * ldc + col0) =
                    make_float2(acc[mt][nt][0] * ia, acc[mt][nt][1] * ia);
                *(float2*)(C + (size_t)(row0 + 8) * ldc + col0) =
                    make_float2(acc[mt][nt][2] * ib, acc[mt][nt][3] * ib);
            }
        }
    }
}

// ===================== fused fp32 -> fp16 convert (x | Wq | Wk | Wv) =========
#define XQUADS (BB * SS * DD / 4)     // 2097152 quads -> 8192 blocks
#define WQUADS (DD * DD / 4)          // 262144 quads  -> 1024 blocks each
__global__ void __launch_bounds__(256) cvt_all_kernel(
    const float* __restrict__ x,  const float* __restrict__ Wq,
    const float* __restrict__ Wk, const float* __restrict__ Wv,
    __half* __restrict__ X16, __half* __restrict__ Wcat)
{
    int blk = blockIdx.x;
    const float* src;
    __half* dst;
    size_t idx;
    if (blk < 8192) {
        src = x; dst = X16;
        idx = (size_t)blk * 256 + threadIdx.x;
    } else {
        int k = blk - 8192;          // 0..3071
        int w = k >> 10;             // which weight
        src = (w == 0) ? Wq : (w == 1) ? Wk : Wv;
        dst = Wcat + (size_t)w * DD * DD;
        idx = (size_t)(k & 1023) * 256 + threadIdx.x;
    }
    float4 v = ((const float4*)src)[idx];
    ((__half2*)dst)[idx * 2]     = __floats2half2_rn(v.x, v.y);
    ((__half2*)dst)[idx * 2 + 1] = __floats2half2_rn(v.z, v.w);
}

// ===================== V (cols 2048.. of QKV) -> V^T (per batch) =============
__global__ void __launch_bounds__(256) transpose16_kernel(
    const __half* __restrict__ QKV, __half* __restrict__ VT)
{
    __shared__ __half t[32][34];
    int z = blockIdx.z;
    const __half* Vb = QKV + (size_t)z * SS * ND3 + 2 * DD;
    __half* VTb = VT + (size_t)z * SS * DD;
    int d0 = blockIdx.x * 32, s0 = blockIdx.y * 32;
    int tx = threadIdx.x & 31, ty = threadIdx.x >> 5;   // 32 x 8
    #pragma unroll
    for (int j = 0; j < 4; j++)
        t[ty + j * 8][tx] = Vb[(size_t)(s0 + ty + j * 8) * ND3 + d0 + tx];
    __syncthreads();
    #pragma unroll
    for (int j = 0; j < 4; j++)
        VTb[(size_t)(d0 + ty + j * 8) * SS + s0 + tx] = t[tx][ty + j * 8];
}

// ===========================================================================
extern "C" void kernel_launch(void* const* d_in, const int* in_sizes, int n_in,
                              void* d_out, int out_size)
{
    const float* x  = (const float*)d_in[0];
    const float* Wq = (const float*)d_in[1];
    const float* Wk = (const float*)d_in[2];
    const float* Wv = (const float*)d_in[3];
    float* out = (float*)d_out;

    __half *X16, *Wcat, *QKV, *VT16, *P16;
    float *rsp;
    cudaGetSymbolAddress((void**)&X16,  g_X16);
    cudaGetSymbolAddress((void**)&Wcat, g_Wcat16);
    cudaGetSymbolAddress((void**)&QKV,  g_QKV16);
    cudaGetSymbolAddress((void**)&VT16, g_VT16);
    cudaGetSymbolAddress((void**)&P16,  g_P16);
    cudaGetSymbolAddress((void**)&rsp,  g_rs);

    cudaFuncSetAttribute(mm_fp16<0, 3, false>,
                         cudaFuncAttributeMaxDynamicSharedMemorySize, SMEM_BYTES);
    cudaFuncSetAttribute(mm_fp16<1, 4, false>,
                         cudaFuncAttributeMaxDynamicSharedMemorySize, SMEM_BYTES);
    cudaFuncSetAttribute(mm_fp16<2, 4, true>,
                         cudaFuncAttributeMaxDynamicSharedMemorySize, SMEM_BYTES);

    const size_t sQKV3 = (size_t)SS * ND3;   // per-batch stride in packed QKV
    const size_t sV    = (size_t)SS * DD;
    const size_t sP    = (size_t)SS * SS;

    // 0) fused fp32 -> fp16 conversion (x + all weights, one launch)
    cvt_all_kernel<<<8192 + 3 * 1024, 256>>>(x, Wq, Wk, Wv, X16, Wcat);

    // 1) Fused QKV projection: [8192, 3072] = X @ Wcat^T, N-tile=96
    dim3 gProj(ND3 / 96, (BB * SS) / 128, 1);
    mm_fp16<0, 3, false><<<gProj, 256, SMEM_BYTES>>>(X16, Wcat, QKV, nullptr, nullptr,
                                                     DD, DD, DD, ND3, 0, 0, 0);

    // 2) V -> V^T (fp16)
    dim3 gT(DD / 32, SS / 32, BB);
    transpose16_kernel<<<gT, 256>>>(QKV, VT16);

    // 3) Scores + exp + mask + row-partial sums; triangular-packed grid
    const int TTILES = (SS / 128) * (SS / 128 + 1) / 2;   // 136
    dim3 gScore(TTILES, 1, BB);
    mm_fp16<1, 4, false><<<gScore, 256, SMEM_BYTES>>>(QKV, QKV + DD, P16, nullptr, rsp,
                                                      DD, ND3, ND3, SS,
                                                      sQKV3, sQKV3, sP);

    // 4) O = diag(1/rowsum) * (P~ @ V)   (inv computed in-kernel from partials)
    dim3 gOut(DD / 128, SS / 128, BB);
    mm_fp16<2, 4, true><<<gOut, 256, SMEM_BYTES>>>(P16, VT16, out, rsp, nullptr,
                                                   SS, SS, SS, DD,
                                                   sP, sV, sV);
}

// round 9
// speedup vs baseline: 8.1994x; 1.0199x over previous
#include <cuda_runtime.h>
#include <cuda_fp16.h>
#include <cstdint>
#include <cstddef>

#define BB 4
#define SS 2048
#define DD 1024
#define ND3 (3 * DD)    // packed QKV width = 3072

// Scratch (__device__ globals; allocation-free rule)
__device__ __half g_X16[BB * SS * DD];
__device__ __half g_Wcat16[ND3 * DD];              // [Wq; Wk; Wv] rows
__device__ __half g_QKV16[(size_t)BB * SS * ND3];  // [B*S, 3072]: Q|K|V
__device__ __half g_VT16[BB * SS * DD];            // per batch [D, S]
__device__ __half g_P16[(size_t)BB * SS * SS];     // unnormalized exp scores
__device__ float  g_rs[BB * SS * 16];              // per-(row, bxTile) partial sums

// exp2 factor: (1/sqrt(1024)) * log2(e)
#define EXPC 0.0450842200277801f

__device__ __forceinline__ uint32_t smem_u32(const void* p) {
    uint32_t a;
    asm("{ .reg .u64 t; cvta.to.shared.u64 t, %1; cvt.u32.u64 %0, t; }" : "=r"(a) : "l"(p));
    return a;
}
__device__ __forceinline__ void cp16(uint32_t dst, const void* src) {
    asm volatile("cp.async.cg.shared.global [%0], [%1], 16;" :: "r"(dst), "l"(src) : "memory");
}
__device__ __forceinline__ void ldsm_x4(uint32_t& r0, uint32_t& r1, uint32_t& r2,
                                        uint32_t& r3, uint32_t addr) {
    asm volatile("ldmatrix.sync.aligned.m8n8.x4.shared.b16 {%0,%1,%2,%3}, [%4];"
                 : "=r"(r0), "=r"(r1), "=r"(r2), "=r"(r3) : "r"(addr));
}
__device__ __forceinline__ void mma_fp16(float c[4], uint32_t a0, uint32_t a1,
                                         uint32_t a2, uint32_t a3,
                                         uint32_t b0, uint32_t b1) {
    asm volatile(
        "mma.sync.aligned.m16n8k16.row.col.f32.f16.f16.f32 "
        "{%0,%1,%2,%3}, {%4,%5,%6,%7}, {%8,%9}, {%0,%1,%2,%3};\n"
        : "+f"(c[0]), "+f"(c[1]), "+f"(c[2]), "+f"(c[3])
        : "r"(a0), "r"(a1), "r"(a2), "r"(a3), "r"(b0), "r"(b1));
}

// ===================== fp16 NT GEMM =====================
// C[m,n] = sum_k A[m,k]*B[n,k]; A:[M,K] rm fp16, B:[N,K] rm fp16.
// CTA tile 128 x (NFRAG*32), BK=64, 256 thr, 3-stage cp.async ring,
// XOR-swizzled smem (128B rows), conflict-free ldmatrix.
// Strides are compile-time (register relief -> 2 CTAs/SM).
// MODE 0: half out (projection)
// MODE 1: half out = exp2(v*EXPC) + causal mask; triangular grid;
//         emits per-row partial sums into g_rs[b][row][bx]
// MODE 2: float out scaled by 1/rowsum (computed from g_rs in prologue)
#define BK 64
#define OPB (128 * 128)               // bytes per operand region
#define STG_BYTES (2 * OPB)           // 32768 per stage
#define STAGES 3
#define SMEM_BYTES (STAGES * STG_BYTES + 512)
#define INV_OFF (STAGES * STG_BYTES)

template<int MODE, int NFRAG, bool KTRUNC,
         int LDA, int LDB, int LDC,
         long long SA, long long SB, long long SC>
__global__ void __launch_bounds__(256, 2) mm_fp16(
    const __half* __restrict__ Ab, const __half* __restrict__ Bb, void* __restrict__ Cb,
    const float* __restrict__ Rs, float* __restrict__ RsOut, int K)
{
    constexpr int NTILE = NFRAG * 32;     // CTA n extent
    constexpr int WN    = NFRAG * 8;      // per-warp n extent

    int bx, by;
    if (MODE == 1) {            // triangular-packed: blockIdx.x -> (bx <= by)
        int t = blockIdx.x;
        by = (int)((sqrtf(8.f * (float)t + 1.f) - 1.f) * 0.5f);
        while ((by + 1) * (by + 2) / 2 <= t) by++;
        while (by * (by + 1) / 2 > t)       by--;
        bx = t - by * (by + 1) / 2;
    } else {
        bx = blockIdx.x;
        by = KTRUNC ? (gridDim.y - 1 - blockIdx.y) : blockIdx.y;
    }

    extern __shared__ __align__(128) char smem[];
    const uint32_t sb = smem_u32(smem);

    const int tid  = threadIdx.x;
    const int wid  = tid >> 5, lane = tid & 31;
    const int wm   = wid & 1;            // warp row -> 64 rows
    const int wn   = wid >> 1;           // warp col -> WN cols
    const int gid  = lane >> 2;
    const int tig  = lane & 3;

    const __half* A = Ab + blockIdx.z * SA + (size_t)by * 128 * LDA;
    const __half* B = Bb + blockIdx.z * SB + (size_t)bx * NTILE * LDB;

    const int kend = KTRUNC ? min(K, (by + 1) * 128) : K;
    const int NC   = kend / BK;          // >= 2 always

    // ldmatrix lane geometry (swizzled col16 index)
    const uint32_t swz    = lane & 7;
    const uint32_t rowA   = wm * 64 + (lane & 15);
    const uint32_t chalfA = lane >> 4;
    const uint32_t rowB   = wn * WN + (lane & 7) + ((lane >> 4) << 3);
    const uint32_t chalfB = (lane >> 3) & 1;

    auto issue_chunk = [&](int c) {
        const int stg = c - (c / 3) * 3;
        const uint32_t ab = sb + stg * STG_BYTES;
        const uint32_t bb = ab + OPB;
        const int k0 = c * BK;
        #pragma unroll
        for (int i = 0; i < 4; i++) {
            int s = tid + i * 256;
            uint32_t r = s >> 3, f = s & 7;
            uint32_t d = r * 128 + ((f ^ (r & 7)) << 4);
            cp16(ab + d, A + (size_t)r * LDA + k0 + f * 8);
        }
        #pragma unroll
        for (int i = 0; i < NFRAG; i++) {
            int s = tid + i * 256;
            uint32_t r = s >> 3, f = s & 7;
            uint32_t d = r * 128 + ((f ^ (r & 7)) << 4);
            cp16(bb + d, B + (size_t)r * LDB + k0 + f * 8);
        }
        asm volatile("cp.async.commit_group;" ::: "memory");
    };

    float acc[4][NFRAG][4];
    #pragma unroll
    for (int i = 0; i < 4; i++)
        #pragma unroll
        for (int j = 0; j < NFRAG; j++)
            #pragma unroll
            for (int t = 0; t < 4; t++) acc[i][j][t] = 0.f;

    issue_chunk(0);
    issue_chunk(1);

    // MODE 2 prologue: compute 1/rowsum for this CTA's 128 rows from partials.
    if (MODE == 2 && tid < 128) {
        const float* rs = Rs + ((size_t)blockIdx.z * SS + by * 128 + tid) * 16;
        float s = 0.f;
        for (int j = 0; j <= by; j++) s += rs[j];
        ((float*)(smem + INV_OFF))[tid] = 1.0f / s;
    }

    for (int c = 0; c < NC; c++) {
        asm volatile("cp.async.wait_group 1;" ::: "memory");   // chunk c arrived
        __syncthreads();
        if (c + 2 < NC) issue_chunk(c + 2);
        else asm volatile("cp.async.commit_group;" ::: "memory");

        const int stg = c - (c / 3) * 3;
        const uint32_t ab = sb + stg * STG_BYTES;
        const uint32_t bb = ab + OPB;

        #pragma unroll
        for (int ks = 0; ks < 4; ks++) {     // four k16 steps per BK=64
            uint32_t afr[4][4], bfr[2][4];
            #pragma unroll
            for (int mt = 0; mt < 4; mt++)
                ldsm_x4(afr[mt][0], afr[mt][1], afr[mt][2], afr[mt][3],
                        ab + (rowA + mt * 16) * 128
                           + ((((ks << 1) | chalfA) ^ swz) << 4));
            #pragma unroll
            for (int nt2 = 0; nt2 < 2; nt2++)
                ldsm_x4(bfr[nt2][0], bfr[nt2][1], bfr[nt2][2], bfr[nt2][3],
                        bb + (rowB + nt2 * 16) * 128
                           + ((((ks << 1) | chalfB) ^ swz) << 4));
            #pragma unroll
            for (int mt = 0; mt < 4; mt++)
                #pragma unroll
                for (int nt = 0; nt < NFRAG; nt++)
                    mma_fp16(acc[mt][nt], afr[mt][0], afr[mt][1], afr[mt][2],
                             afr[mt][3], bfr[nt >> 1][(nt & 1) * 2],
                             bfr[nt >> 1][(nt & 1) * 2 + 1]);
        }
    }

    // Epilogue
    if (MODE == 0) {
        __half* C = (__half*)Cb + blockIdx.z * SC + (size_t)by * 128 * LDC
                  + (size_t)bx * NTILE;
        #pragma unroll
        for (int mt = 0; mt < 4; mt++) {
            int row0 = wm * 64 + mt * 16 + gid;
            #pragma unroll
            for (int nt = 0; nt < NFRAG; nt++) {
                int col0 = wn * WN + nt * 8 + tig * 2;
                *(__half2*)(C + (size_t)row0       * LDC + col0) =
                    __floats2half2_rn(acc[mt][nt][0], acc[mt][nt][1]);
                *(__half2*)(C + (size_t)(row0 + 8) * LDC + col0) =
                    __floats2half2_rn(acc[mt][nt][2], acc[mt][nt][3]);
            }
        }
    } else if (MODE == 1) {
        __half* C = (__half*)Cb + blockIdx.z * SC + (size_t)by * 128 * LDC
                  + (size_t)bx * NTILE;
        float srow[4][2];                       // per-thread row partials per mt
        #pragma unroll
        for (int mt = 0; mt < 4; mt++) { srow[mt][0] = 0.f; srow[mt][1] = 0.f; }

        #pragma unroll
        for (int mt = 0; mt < 4; mt++) {
            int row0 = wm * 64 + mt * 16 + gid;
            int grow0 = by * 128 + row0;        // q
            #pragma unroll
            for (int nt = 0; nt < NFRAG; nt++) {
                int col0 = wn * WN + nt * 8 + tig * 2;
                int gcol0 = bx * NTILE + col0;  // k
                float v0 = (gcol0     <= grow0)     ? exp2f(acc[mt][nt][0] * EXPC) : 0.f;
                float v1 = (gcol0 + 1 <= grow0)     ? exp2f(acc[mt][nt][1] * EXPC) : 0.f;
                float v2 = (gcol0     <= grow0 + 8) ? exp2f(acc[mt][nt][2] * EXPC) : 0.f;
                float v3 = (gcol0 + 1 <= grow0 + 8) ? exp2f(acc[mt][nt][3] * EXPC) : 0.f;
                srow[mt][0] += v0 + v1;
                srow[mt][1] += v2 + v3;
                *(__half2*)(C + (size_t)row0       * LDC + col0) = __floats2half2_rn(v0, v1);
                *(__half2*)(C + (size_t)(row0 + 8) * LDC + col0) = __floats2half2_rn(v2, v3);
            }
        }
        // reduce across the 4 tig lanes of each row group
        #pragma unroll
        for (int mt = 0; mt < 4; mt++) {
            #pragma unroll
            for (int h = 0; h < 2; h++) {
                float s = srow[mt][h];
                s += __shfl_xor_sync(0xFFFFFFFFu, s, 1);
                s += __shfl_xor_sync(0xFFFFFFFFu, s, 2);
                srow[mt][h] = s;
            }
        }
        __syncthreads();                        // pipeline smem no longer needed
        float* part = (float*)smem;             // [128][4]
        if (tig == 0) {
            #pragma unroll
            for (int mt = 0; mt < 4; mt++) {
                int rl = wm * 64 + mt * 16 + gid;
                part[rl * 4 + wn]       = srow[mt][0];
                part[(rl + 8) * 4 + wn] = srow[mt][1];
            }
        }
        __syncthreads();
        if (tid < 128) {
            float s = part[tid * 4] + part[tid * 4 + 1]
                    + part[tid * 4 + 2] + part[tid * 4 + 3];
            RsOut[((size_t)blockIdx.z * SS + by * 128 + tid) * 16 + bx] = s;
        }
    } else {
        float* C = (float*)Cb + blockIdx.z * SC + (size_t)by * 128 * LDC
                 + (size_t)bx * NTILE;
        const float* invs = (const float*)(smem + INV_OFF);
        #pragma unroll
        for (int mt = 0; mt < 4; mt++) {
            int row0 = wm * 64 + mt * 16 + gid;
            float ia = invs[row0];
            float ib = invs[row0 + 8];
            #pragma unroll
            for (int nt = 0; nt < NFRAG; nt++) {
                int col0 = wn * WN + nt * 8 + tig * 2;
                *(float2*)(C + (size_t)row0       * LDC + col0) =
                    make_float2(acc[mt][nt][0] * ia, acc[mt][nt][1] * ia);
                *(float2*)(C + (size_t)(row0 + 8) * LDC + col0) =
                    make_float2(acc[mt][nt][2] * ib, acc[mt][nt][3] * ib);
            }
        }
    }
}

// ===================== fused fp32 -> fp16 convert (x | Wq | Wk | Wv) =========
__global__ void __launch_bounds__(256) cvt_all_kernel(
    const float* __restrict__ x,  const float* __restrict__ Wq,
    const float* __restrict__ Wk, const float* __restrict__ Wv,
    __half* __restrict__ X16, __half* __restrict__ Wcat)
{
    int blk = blockIdx.x;
    const float* src;
    __half* dst;
    size_t idx;
    if (blk < 8192) {
        src = x; dst = X16;
        idx = (size_t)blk * 256 + threadIdx.x;
    } else {
        int k = blk - 8192;          // 0..3071
        int w = k >> 10;             // which weight
        src = (w == 0) ? Wq : (w == 1) ? Wk : Wv;
        dst = Wcat + (size_t)w * DD * DD;
        idx = (size_t)(k & 1023) * 256 + threadIdx.x;
    }
    float4 v = ((const float4*)src)[idx];
    ((__half2*)dst)[idx * 2]     = __floats2half2_rn(v.x, v.y);
    ((__half2*)dst)[idx * 2 + 1] = __floats2half2_rn(v.z, v.w);
}

// ===================== V (cols 2048.. of QKV) -> V^T (per batch) =============
__global__ void __launch_bounds__(256) transpose16_kernel(
    const __half* __restrict__ QKV, __half* __restrict__ VT)
{
    __shared__ __half t[32][34];
    int z = blockIdx.z;
    const __half* Vb = QKV + (size_t)z * SS * ND3 + 2 * DD;
    __half* VTb = VT + (size_t)z * SS * DD;
    int d0 = blockIdx.x * 32, s0 = blockIdx.y * 32;
    int tx = threadIdx.x & 31, ty = threadIdx.x >> 5;   // 32 x 8
    #pragma unroll
    for (int j = 0; j < 4; j++)
        t[ty + j * 8][tx] = Vb[(size_t)(s0 + ty + j * 8) * ND3 + d0 + tx];
    __syncthreads();
    #pragma unroll
    for (int j = 0; j < 4; j++)
        VTb[(size_t)(d0 + ty + j * 8) * SS + s0 + tx] = t[tx][ty + j * 8];
}

// ===========================================================================
extern "C" void kernel_launch(void* const* d_in, const int* in_sizes, int n_in,
                              void* d_out, int out_size)
{
    const float* x  = (const float*)d_in[0];
    const float* Wq = (const float*)d_in[1];
    const float* Wk = (const float*)d_in[2];
    const float* Wv = (const float*)d_in[3];
    float* out = (float*)d_out;

    __half *X16, *Wcat, *QKV, *VT16, *P16;
    float *rsp;
    cudaGetSymbolAddress((void**)&X16,  g_X16);
    cudaGetSymbolAddress((void**)&Wcat, g_Wcat16);
    cudaGetSymbolAddress((void**)&QKV,  g_QKV16);
    cudaGetSymbolAddress((void**)&VT16, g_VT16);
    cudaGetSymbolAddress((void**)&P16,  g_P16);
    cudaGetSymbolAddress((void**)&rsp,  g_rs);

    constexpr long long sQKV3 = (long long)SS * ND3;   // per-batch stride, packed QKV
    constexpr long long sV    = (long long)SS * DD;
    constexpr long long sP    = (long long)SS * SS;

    auto kProj  = mm_fp16<0, 3, false, DD,  DD,  ND3, 0,     0,     0>;
    auto kScore = mm_fp16<1, 4, false, ND3, ND3, SS,  sQKV3, sQKV3, sP>;
    auto kOut   = mm_fp16<2, 4, true,  SS,  SS,  DD,  sP,    sV,    sV>;

    cudaFuncSetAttribute(kProj,  cudaFuncAttributeMaxDynamicSharedMemorySize, SMEM_BYTES);
    cudaFuncSetAttribute(kScore, cudaFuncAttributeMaxDynamicSharedMemorySize, SMEM_BYTES);
    cudaFuncSetAttribute(kOut,   cudaFuncAttributeMaxDynamicSharedMemorySize, SMEM_BYTES);

    // 0) fused fp32 -> fp16 conversion (x + all weights, one launch)
    cvt_all_kernel<<<8192 + 3 * 1024, 256>>>(x, Wq, Wk, Wv, X16, Wcat);

    // 1) Fused QKV projection: [8192, 3072] = X @ Wcat^T, N-tile=96
    dim3 gProj(ND3 / 96, (BB * SS) / 128, 1);
    kProj<<<gProj, 256, SMEM_BYTES>>>(X16, Wcat, QKV, nullptr, nullptr, DD);

    // 2) V -> V^T (fp16)
    dim3 gT(DD / 32, SS / 32, BB);
    transpose16_kernel<<<gT, 256>>>(QKV, VT16);

    // 3) Scores + exp + mask + row-partial sums; triangular-packed grid
    const int TTILES = (SS / 128) * (SS / 128 + 1) / 2;   // 136
    dim3 gScore(TTILES, 1, BB);
    kScore<<<gScore, 256, SMEM_BYTES>>>(QKV, QKV + DD, P16, nullptr, rsp, DD);

    // 4) O = diag(1/rowsum) * (P~ @ V)   (inv computed in-kernel from partials)
    dim3 gOut(DD / 128, SS / 128, BB);
    kOut<<<gOut, 256, SMEM_BYTES>>>(P16, VT16, out, rsp, nullptr, SS);
}

// round 10
// speedup vs baseline: 8.9073x; 1.0863x over previous
#include <cuda_runtime.h>
#include <cuda_fp16.h>
#include <cstdint>
#include <cstddef>

#define BB 4
#define SS 2048
#define DD 1024
#define ND3 (3 * DD)    // packed QKV width = 3072

// Scratch (__device__ globals; allocation-free rule)
__device__ __half g_X16[BB * SS * DD];
__device__ __half g_Wcat16[ND3 * DD];              // [Wq; Wk; Wv] rows
__device__ __half g_QKV16[(size_t)BB * SS * ND3];  // [B*S, 3072]: Q|K|(V unused)
__device__ __half g_VT16[BB * SS * DD];            // per batch [D, S]
__device__ __half g_P16[(size_t)BB * SS * SS];     // unnormalized exp scores
__device__ float  g_rs[BB * SS * 16];              // per-(row, bxTile) partial sums

// exp2 factor: (1/sqrt(1024)) * log2(e)
#define EXPC 0.0450842200277801f

__device__ __forceinline__ uint32_t smem_u32(const void* p) {
    uint32_t a;
    asm("{ .reg .u64 t; cvta.to.shared.u64 t, %1; cvt.u32.u64 %0, t; }" : "=r"(a) : "l"(p));
    return a;
}
__device__ __forceinline__ void cp16(uint32_t dst, const void* src) {
    asm volatile("cp.async.cg.shared.global [%0], [%1], 16;" :: "r"(dst), "l"(src) : "memory");
}
__device__ __forceinline__ void ldsm_x4(uint32_t& r0, uint32_t& r1, uint32_t& r2,
                                        uint32_t& r3, uint32_t addr) {
    asm volatile("ldmatrix.sync.aligned.m8n8.x4.shared.b16 {%0,%1,%2,%3}, [%4];"
                 : "=r"(r0), "=r"(r1), "=r"(r2), "=r"(r3) : "r"(addr));
}
__device__ __forceinline__ void mma_fp16(float c[4], uint32_t a0, uint32_t a1,
                                         uint32_t a2, uint32_t a3,
                                         uint32_t b0, uint32_t b1) {
    asm volatile(
        "mma.sync.aligned.m16n8k16.row.col.f32.f16.f16.f32 "
        "{%0,%1,%2,%3}, {%4,%5,%6,%7}, {%8,%9}, {%0,%1,%2,%3};\n"
        : "+f"(c[0]), "+f"(c[1]), "+f"(c[2]), "+f"(c[3])
        : "r"(a0), "r"(a1), "r"(a2), "r"(a3), "r"(b0), "r"(b1));
}

// ===================== fp16 NT GEMM =====================
// C[m,n] = sum_k A[m,k]*B[n,k]; A:[M,K] rm fp16, B:[N,K] rm fp16.
// CTA tile 128 x (NFRAG*32), BK=64, 256 thr, 3-stage cp.async ring,
// XOR-swizzled smem (128B rows), conflict-free ldmatrix, compile-time strides.
// MODE 0: half out (projection); V columns (>= 2*DD) written TRANSPOSED to VT.
// MODE 1: half out = exp2(v*EXPC) + causal mask; triangular grid;
//         emits per-row partial sums into g_rs[b][row][bx]
// MODE 2: float out scaled by 1/rowsum; heavy-first 1D grid decode
#define BK 64
#define OPB (128 * 128)               // bytes per operand region
#define STG_BYTES (2 * OPB)           // 32768 per stage
#define STAGES 3
#define SMEM_BYTES (STAGES * STG_BYTES + 512)
#define INV_OFF (STAGES * STG_BYTES)

template<int MODE, int NFRAG, bool KTRUNC,
         int LDA, int LDB, int LDC,
         long long SA, long long SB, long long SC>
__global__ void __launch_bounds__(256, 2) mm_fp16(
    const __half* __restrict__ Ab, const __half* __restrict__ Bb, void* __restrict__ Cb,
    const float* __restrict__ Rs, float* __restrict__ RsOut,
    __half* __restrict__ VTOut, int K)
{
    constexpr int NTILE = NFRAG * 32;     // CTA n extent
    constexpr int WN    = NFRAG * 8;      // per-warp n extent

    int bx, by, bz;
    if (MODE == 1) {            // triangular-packed: blockIdx.x -> (bx <= by)
        int t = blockIdx.x;
        by = (int)((sqrtf(8.f * (float)t + 1.f) - 1.f) * 0.5f);
        while ((by + 1) * (by + 2) / 2 <= t) by++;
        while (by * (by + 1) / 2 > t)       by--;
        bx = t - by * (by + 1) / 2;
        bz = blockIdx.z;
    } else if (MODE == 2) {     // heavy-first 1D: all (bx,z) of a K-level adjacent
        int i = blockIdx.x;
        by = (SS / 128 - 1) - (i >> 5);
        int inner = i & 31;
        bz = inner >> 3;
        bx = inner & 7;
    } else {
        bx = blockIdx.x; by = blockIdx.y; bz = blockIdx.z;
    }

    extern __shared__ __align__(128) char smem[];
    const uint32_t sb = smem_u32(smem);

    const int tid  = threadIdx.x;
    const int wid  = tid >> 5, lane = tid & 31;
    const int wm   = wid & 1;            // warp row -> 64 rows
    const int wn   = wid >> 1;           // warp col -> WN cols
    const int gid  = lane >> 2;
    const int tig  = lane & 3;

    const __half* A = Ab + bz * SA + (size_t)by * 128 * LDA;
    const __half* B = Bb + bz * SB + (size_t)bx * NTILE * LDB;

    const int kend = KTRUNC ? min(K, (by + 1) * 128) : K;
    const int NC   = kend / BK;          // >= 2 always

    // ldmatrix lane geometry (swizzled col16 index)
    const uint32_t swz    = lane & 7;
    const uint32_t rowA   = wm * 64 + (lane & 15);
    const uint32_t chalfA = lane >> 4;
    const uint32_t rowB   = wn * WN + (lane & 7) + ((lane >> 4) << 3);
    const uint32_t chalfB = (lane >> 3) & 1;

    auto issue_chunk = [&](int c) {
        const int stg = c - (c / 3) * 3;
        const uint32_t ab = sb + stg * STG_BYTES;
        const uint32_t bb = ab + OPB;
        const int k0 = c * BK;
        #pragma unroll
        for (int i = 0; i < 4; i++) {
            int s = tid + i * 256;
            uint32_t r = s >> 3, f = s & 7;
            uint32_t d = r * 128 + ((f ^ (r & 7)) << 4);
            cp16(ab + d, A + (size_t)r * LDA + k0 + f * 8);
        }
        #pragma unroll
        for (int i = 0; i < NFRAG; i++) {
            int s = tid + i * 256;
            uint32_t r = s >> 3, f = s & 7;
            uint32_t d = r * 128 + ((f ^ (r & 7)) << 4);
            cp16(bb + d, B + (size_t)r * LDB + k0 + f * 8);
        }
        asm volatile("cp.async.commit_group;" ::: "memory");
    };

    float acc[4][NFRAG][4];
    #pragma unroll
    for (int i = 0; i < 4; i++)
        #pragma unroll
        for (int j = 0; j < NFRAG; j++)
            #pragma unroll
            for (int t = 0; t < 4; t++) acc[i][j][t] = 0.f;

    issue_chunk(0);
    issue_chunk(1);

    // MODE 2 prologue: compute 1/rowsum for this CTA's 128 rows from partials.
    if (MODE == 2 && tid < 128) {
        const float* rs = Rs + ((size_t)bz * SS + by * 128 + tid) * 16;
        float s = 0.f;
        for (int j = 0; j <= by; j++) s += rs[j];
        ((float*)(smem + INV_OFF))[tid] = 1.0f / s;
    }

    for (int c = 0; c < NC; c++) {
        asm volatile("cp.async.wait_group 1;" ::: "memory");   // chunk c arrived
        __syncthreads();
        if (c + 2 < NC) issue_chunk(c + 2);
        else asm volatile("cp.async.commit_group;" ::: "memory");

        const int stg = c - (c / 3) * 3;
        const uint32_t ab = sb + stg * STG_BYTES;
        const uint32_t bb = ab + OPB;

        #pragma unroll
        for (int ks = 0; ks < 4; ks++) {     // four k16 steps per BK=64
            uint32_t afr[4][4], bfr[2][4];
            #pragma unroll
            for (int mt = 0; mt < 4; mt++)
                ldsm_x4(afr[mt][0], afr[mt][1], afr[mt][2], afr[mt][3],
                        ab + (rowA + mt * 16) * 128
                           + ((((ks << 1) | chalfA) ^ swz) << 4));
            #pragma unroll
            for (int nt2 = 0; nt2 < 2; nt2++)
                ldsm_x4(bfr[nt2][0], bfr[nt2][1], bfr[nt2][2], bfr[nt2][3],
                        bb + (rowB + nt2 * 16) * 128
                           + ((((ks << 1) | chalfB) ^ swz) << 4));
            #pragma unroll
            for (int mt = 0; mt < 4; mt++)
                #pragma unroll
                for (int nt = 0; nt < NFRAG; nt++)
                    mma_fp16(acc[mt][nt], afr[mt][0], afr[mt][1], afr[mt][2],
                             afr[mt][3], bfr[nt >> 1][(nt & 1) * 2],
                             bfr[nt >> 1][(nt & 1) * 2 + 1]);
        }
    }

    // Epilogue
    if (MODE == 0) {
        // tiles with any V columns (global col >= 2*DD) also emit V^T
        const bool vtile = (bx * NTILE + NTILE - 1) >= 2 * DD;
        __half* C = (__half*)Cb + bz * SC + (size_t)by * 128 * LDC
                  + (size_t)bx * NTILE;
        #pragma unroll
        for (int mt = 0; mt < 4; mt++) {
            int row0 = wm * 64 + mt * 16 + gid;
            #pragma unroll
            for (int nt = 0; nt < NFRAG; nt++) {
                int col0 = wn * WN + nt * 8 + tig * 2;
                if (!vtile || bx * NTILE + col0 < 2 * DD) {
                    *(__half2*)(C + (size_t)row0       * LDC + col0) =
                        __floats2half2_rn(acc[mt][nt][0], acc[mt][nt][1]);
                    *(__half2*)(C + (size_t)(row0 + 8) * LDC + col0) =
                        __floats2half2_rn(acc[mt][nt][2], acc[mt][nt][3]);
                }
            }
        }
        if (vtile) {
            __syncthreads();                 // pipeline smem no longer needed
            __half* smt = (__half*)smem;     // [NTILE][128]
            #pragma unroll
            for (int mt = 0; mt < 4; mt++) {
                int row0 = wm * 64 + mt * 16 + gid;
                #pragma unroll
                for (int nt = 0; nt < NFRAG; nt++) {
                    int col0 = wn * WN + nt * 8 + tig * 2;
                    smt[(col0)     * 128 + row0]     = __float2half_rn(acc[mt][nt][0]);
                    smt[(col0 + 1) * 128 + row0]     = __float2half_rn(acc[mt][nt][1]);
                    smt[(col0)     * 128 + row0 + 8] = __float2half_rn(acc[mt][nt][2]);
                    smt[(col0 + 1) * 128 + row0 + 8] = __float2half_rn(acc[mt][nt][3]);
                }
            }
            __syncthreads();
            int b  = by >> 4;                // batch (128 rows never straddle)
            int s0 = (by & 15) * 128;
            __half* VTb = VTOut + (size_t)b * SS * DD;
            for (int i = tid; i < NTILE * 16; i += 256) {
                int c2 = i >> 4, ch = i & 15;
                int gcol = bx * NTILE + c2;
                if (gcol >= 2 * DD) {
                    uint4 v = ((const uint4*)(smt + c2 * 128))[ch];
                    *(uint4*)(VTb + (size_t)(gcol - 2 * DD) * SS + s0 + ch * 8) = v;
                }
            }
        }
    } else if (MODE == 1) {
        __half* C = (__half*)Cb + bz * SC + (size_t)by * 128 * LDC
                  + (size_t)bx * NTILE;
        float srow[4][2];                       // per-thread row partials per mt
        #pragma unroll
        for (int mt = 0; mt < 4; mt++) { srow[mt][0] = 0.f; srow[mt][1] = 0.f; }

        #pragma unroll
        for (int mt = 0; mt < 4; mt++) {
            int row0 = wm * 64 + mt * 16 + gid;
            int grow0 = by * 128 + row0;        // q
            #pragma unroll
            for (int nt = 0; nt < NFRAG; nt++) {
                int col0 = wn * WN + nt * 8 + tig * 2;
                int gcol0 = bx * NTILE + col0;  // k
                float v0 = (gcol0     <= grow0)     ? exp2f(acc[mt][nt][0] * EXPC) : 0.f;
                float v1 = (gcol0 + 1 <= grow0)     ? exp2f(acc[mt][nt][1] * EXPC) : 0.f;
                float v2 = (gcol0     <= grow0 + 8) ? exp2f(acc[mt][nt][2] * EXPC) : 0.f;
                float v3 = (gcol0 + 1 <= grow0 + 8) ? exp2f(acc[mt][nt][3] * EXPC) : 0.f;
                srow[mt][0] += v0 + v1;
                srow[mt][1] += v2 + v3;
                *(__half2*)(C + (size_t)row0       * LDC + col0) = __floats2half2_rn(v0, v1);
                *(__half2*)(C + (size_t)(row0 + 8) * LDC + col0) = __floats2half2_rn(v2, v3);
            }
        }
        // reduce across the 4 tig lanes of each row group
        #pragma unroll
        for (int mt = 0; mt < 4; mt++) {
            #pragma unroll
            for (int h = 0; h < 2; h++) {
                float s = srow[mt][h];
                s += __shfl_xor_sync(0xFFFFFFFFu, s, 1);
                s += __shfl_xor_sync(0xFFFFFFFFu, s, 2);
                srow[mt][h] = s;
            }
        }
        __syncthreads();                        // pipeline smem no longer needed
        float* part = (float*)smem;             // [128][4]
        if (tig == 0) {
            #pragma unroll
            for (int mt = 0; mt < 4; mt++) {
                int rl = wm * 64 + mt * 16 + gid;
                part[rl * 4 + wn]       = srow[mt][0];
                part[(rl + 8) * 4 + wn] = srow[mt][1];
            }
        }
        __syncthreads();
        if (tid < 128) {
            float s = part[tid * 4] + part[tid * 4 + 1]
                    + part[tid * 4 + 2] + part[tid * 4 + 3];
            RsOut[((size_t)bz * SS + by * 128 + tid) * 16 + bx] = s;
        }
    } else {
        float* C = (float*)Cb + bz * SC + (size_t)by * 128 * LDC
                 + (size_t)bx * NTILE;
        const float* invs = (const float*)(smem + INV_OFF);
        #pragma unroll
        for (int mt = 0; mt < 4; mt++) {
            int row0 = wm * 64 + mt * 16 + gid;
            float ia = invs[row0];
            float ib = invs[row0 + 8];
            #pragma unroll
            for (int nt = 0; nt < NFRAG; nt++) {
                int col0 = wn * WN + nt * 8 + tig * 2;
                *(float2*)(C + (size_t)row0       * LDC + col0) =
                    make_float2(acc[mt][nt][0] * ia, acc[mt][nt][1] * ia);
                *(float2*)(C + (size_t)(row0 + 8) * LDC + col0) =
                    make_float2(acc[mt][nt][2] * ib, acc[mt][nt][3] * ib);
            }
        }
    }
}

// ===================== fused fp32 -> fp16 convert (x | Wq | Wk | Wv) =========
__global__ void __launch_bounds__(256) cvt_all_kernel(
    const float* __restrict__ x,  const float* __restrict__ Wq,
    const float* __restrict__ Wk, const float* __restrict__ Wv,
    __half* __restrict__ X16, __half* __restrict__ Wcat)
{
    int blk = blockIdx.x;
    const float* src;
    __half* dst;
    size_t idx;
    if (blk < 8192) {
        src = x; dst = X16;
        idx = (size_t)blk * 256 + threadIdx.x;
    } else {
        int k = blk - 8192;          // 0..3071
        int w = k >> 10;             // which weight
        src = (w == 0) ? Wq : (w == 1) ? Wk : Wv;
        dst = Wcat + (size_t)w * DD * DD;
        idx = (size_t)(k & 1023) * 256 + threadIdx.x;
    }
    float4 v = ((const float4*)src)[idx];
    ((__half2*)dst)[idx * 2]     = __floats2half2_rn(v.x, v.y);
    ((__half2*)dst)[idx * 2 + 1] = __floats2half2_rn(v.z, v.w);
}

// ===========================================================================
extern "C" void kernel_launch(void* const* d_in, const int* in_sizes, int n_in,
                              void* d_out, int out_size)
{
    const float* x  = (const float*)d_in[0];
    const float* Wq = (const float*)d_in[1];
    const float* Wk = (const float*)d_in[2];
    const float* Wv = (const float*)d_in[3];
    float* out = (float*)d_out;

    __half *X16, *Wcat, *QKV, *VT16, *P16;
    float *rsp;
    cudaGetSymbolAddress((void**)&X16,  g_X16);
    cudaGetSymbolAddress((void**)&Wcat, g_Wcat16);
    cudaGetSymbolAddress((void**)&QKV,  g_QKV16);
    cudaGetSymbolAddress((void**)&VT16, g_VT16);
    cudaGetSymbolAddress((void**)&P16,  g_P16);
    cudaGetSymbolAddress((void**)&rsp,  g_rs);

    constexpr long long sQKV3 = (long long)SS * ND3;   // per-batch stride, packed QKV
    constexpr long long sV    = (long long)SS * DD;
    constexpr long long sP    = (long long)SS * SS;

    auto kProj  = mm_fp16<0, 3, false, DD,  DD,  ND3, 0,     0,     0>;
    auto kScore = mm_fp16<1, 4, false, ND3, ND3, SS,  sQKV3, sQKV3, sP>;
    auto kOut   = mm_fp16<2, 4, true,  SS,  SS,  DD,  sP,    sV,    sV>;

    cudaFuncSetAttribute(kProj,  cudaFuncAttributeMaxDynamicSharedMemorySize, SMEM_BYTES);
    cudaFuncSetAttribute(kScore, cudaFuncAttributeMaxDynamicSharedMemorySize, SMEM_BYTES);
    cudaFuncSetAttribute(kOut,   cudaFuncAttributeMaxDynamicSharedMemorySize, SMEM_BYTES);

    // 0) fused fp32 -> fp16 conversion (x + all weights, one launch)
    cvt_all_kernel<<<8192 + 3 * 1024, 256>>>(x, Wq, Wk, Wv, X16, Wcat);

    // 1) Fused QKV projection; V columns written transposed to VT16
    dim3 gProj(ND3 / 96, (BB * SS) / 128, 1);
    kProj<<<gProj, 256, SMEM_BYTES>>>(X16, Wcat, QKV, nullptr, nullptr, VT16, DD);

    // 2) Scores + exp + mask + row-partial sums; triangular-packed grid
    const int TTILES = (SS / 128) * (SS / 128 + 1) / 2;   // 136
    dim3 gScore(TTILES, 1, BB);
    kScore<<<gScore, 256, SMEM_BYTES>>>(QKV, QKV + DD, P16, nullptr, rsp, nullptr, DD);

    // 3) O = diag(1/rowsum) * (P~ @ V); heavy-first 1D grid
    dim3 gOut((DD / 128) * (SS / 128) * BB, 1, 1);
    kOut<<<gOut, 256, SMEM_BYTES>>>(P16, VT16, out, rsp, nullptr, nullptr, SS);
}

// round 11
// speedup vs baseline: 8.9515x; 1.0050x over previous
#include <cuda_runtime.h>
#include <cuda_fp16.h>
#include <cstdint>
#include <cstddef>

#define BB 4
#define SS 2048
#define DD 1024
#define ND3 (3 * DD)    // packed QKV width = 3072

// Scratch (__device__ globals; allocation-free rule)
__device__ __half g_X16[BB * SS * DD];
__device__ __half g_Wcat16[ND3 * DD];              // [Wq; Wk; Wv] rows
__device__ __half g_QKV16[(size_t)BB * SS * ND3];  // [B*S, 3072]: Q|K|(V unused)
__device__ __half g_VT16[BB * SS * DD];            // per batch [D, S]
__device__ __half g_P16[(size_t)BB * SS * SS];     // unnormalized exp scores
__device__ float  g_rs[BB * SS * 16];              // per-(row, bxTile) partial sums

// exp2 factor: (1/sqrt(1024)) * log2(e)
#define EXPC 0.0450842200277801f

__device__ __forceinline__ uint32_t smem_u32(const void* p) {
    uint32_t a;
    asm("{ .reg .u64 t; cvta.to.shared.u64 t, %1; cvt.u32.u64 %0, t; }" : "=r"(a) : "l"(p));
    return a;
}
__device__ __forceinline__ void cp16(uint32_t dst, const void* src) {
    asm volatile("cp.async.cg.shared.global [%0], [%1], 16;" :: "r"(dst), "l"(src) : "memory");
}
__device__ __forceinline__ void ldsm_x4(uint32_t& r0, uint32_t& r1, uint32_t& r2,
                                        uint32_t& r3, uint32_t addr) {
    asm volatile("ldmatrix.sync.aligned.m8n8.x4.shared.b16 {%0,%1,%2,%3}, [%4];"
                 : "=r"(r0), "=r"(r1), "=r"(r2), "=r"(r3) : "r"(addr));
}
__device__ __forceinline__ void mma_fp16(float c[4], uint32_t a0, uint32_t a1,
                                         uint32_t a2, uint32_t a3,
                                         uint32_t b0, uint32_t b1) {
    asm volatile(
        "mma.sync.aligned.m16n8k16.row.col.f32.f16.f16.f32 "
        "{%0,%1,%2,%3}, {%4,%5,%6,%7}, {%8,%9}, {%0,%1,%2,%3};\n"
        : "+f"(c[0]), "+f"(c[1]), "+f"(c[2]), "+f"(c[3])
        : "r"(a0), "r"(a1), "r"(a2), "r"(a3), "r"(b0), "r"(b1));
}

#define BK 64
#define OPB (128 * 128)               // bytes per operand region
#define STG_BYTES (2 * OPB)           // 32768 per stage
#define STAGES 3
#define SMEM_BYTES (STAGES * STG_BYTES + 512)
#define INV_OFF (STAGES * STG_BYTES)

// ===================== PROJECTION GEMM (proven R10 config) ==================
// 256 thr, 8 warps of 64x32, CTA 128x96 (NFRAG=3). V cols -> VT transposed.
template<int NFRAG, int LDA, int LDB, int LDC>
__global__ void __launch_bounds__(256, 2) mm_proj(
    const __half* __restrict__ Ab, const __half* __restrict__ Bb,
    __half* __restrict__ Cb, __half* __restrict__ VTOut, int K)
{
    constexpr int NTILE = NFRAG * 32;
    constexpr int WN    = NFRAG * 8;
    const int bx = blockIdx.x, by = blockIdx.y;

    extern __shared__ __align__(128) char smem[];
    const uint32_t sb = smem_u32(smem);

    const int tid  = threadIdx.x;
    const int wid  = tid >> 5, lane = tid & 31;
    const int wm   = wid & 1;
    const int wn   = wid >> 1;
    const int gid  = lane >> 2;
    const int tig  = lane & 3;

    const __half* A = Ab + (size_t)by * 128 * LDA;
    const __half* B = Bb + (size_t)bx * NTILE * LDB;
    const int NC = K / BK;

    const uint32_t swz    = lane & 7;
    const uint32_t rowA   = wm * 64 + (lane & 15);
    const uint32_t chalfA = lane >> 4;
    const uint32_t rowB   = wn * WN + (lane & 7) + ((lane >> 4) << 3);
    const uint32_t chalfB = (lane >> 3) & 1;

    auto issue_chunk = [&](int c) {
        const int stg = c - (c / 3) * 3;
        const uint32_t ab = sb + stg * STG_BYTES;
        const uint32_t bb = ab + OPB;
        const int k0 = c * BK;
        #pragma unroll
        for (int i = 0; i < 4; i++) {
            int s = tid + i * 256;
            uint32_t r = s >> 3, f = s & 7;
            uint32_t d = r * 128 + ((f ^ (r & 7)) << 4);
            cp16(ab + d, A + (size_t)r * LDA + k0 + f * 8);
        }
        #pragma unroll
        for (int i = 0; i < NFRAG; i++) {
            int s = tid + i * 256;
            uint32_t r = s >> 3, f = s & 7;
            uint32_t d = r * 128 + ((f ^ (r & 7)) << 4);
            cp16(bb + d, B + (size_t)r * LDB + k0 + f * 8);
        }
        asm volatile("cp.async.commit_group;" ::: "memory");
    };

    float acc[4][NFRAG][4];
    #pragma unroll
    for (int i = 0; i < 4; i++)
        #pragma unroll
        for (int j = 0; j < NFRAG; j++)
            #pragma unroll
            for (int t = 0; t < 4; t++) acc[i][j][t] = 0.f;

    issue_chunk(0); issue_chunk(1);

    for (int c = 0; c < NC; c++) {
        asm volatile("cp.async.wait_group 1;" ::: "memory");
        __syncthreads();
        if (c + 2 < NC) issue_chunk(c + 2);
        else asm volatile("cp.async.commit_group;" ::: "memory");

        const int stg = c - (c / 3) * 3;
        const uint32_t ab = sb + stg * STG_BYTES;
        const uint32_t bb = ab + OPB;

        #pragma unroll
        for (int ks = 0; ks < 4; ks++) {
            uint32_t afr[4][4], bfr[2][4];
            #pragma unroll
            for (int mt = 0; mt < 4; mt++)
                ldsm_x4(afr[mt][0], afr[mt][1], afr[mt][2], afr[mt][3],
                        ab + (rowA + mt * 16) * 128
                           + ((((ks << 1) | chalfA) ^ swz) << 4));
            #pragma unroll
            for (int nt2 = 0; nt2 < 2; nt2++)
                ldsm_x4(bfr[nt2][0], bfr[nt2][1], bfr[nt2][2], bfr[nt2][3],
                        bb + (rowB + nt2 * 16) * 128
                           + ((((ks << 1) | chalfB) ^ swz) << 4));
            #pragma unroll
            for (int mt = 0; mt < 4; mt++)
                #pragma unroll
                for (int nt = 0; nt < NFRAG; nt++)
                    mma_fp16(acc[mt][nt], afr[mt][0], afr[mt][1], afr[mt][2],
                             afr[mt][3], bfr[nt >> 1][(nt & 1) * 2],
                             bfr[nt >> 1][(nt & 1) * 2 + 1]);
        }
    }

    const bool vtile = (bx * NTILE + NTILE - 1) >= 2 * DD;
    __half* C = Cb + (size_t)by * 128 * LDC + (size_t)bx * NTILE;
    #pragma unroll
    for (int mt = 0; mt < 4; mt++) {
        int row0 = wm * 64 + mt * 16 + gid;
        #pragma unroll
        for (int nt = 0; nt < NFRAG; nt++) {
            int col0 = wn * WN + nt * 8 + tig * 2;
            if (!vtile || bx * NTILE + col0 < 2 * DD) {
                *(__half2*)(C + (size_t)row0       * LDC + col0) =
                    __floats2half2_rn(acc[mt][nt][0], acc[mt][nt][1]);
                *(__half2*)(C + (size_t)(row0 + 8) * LDC + col0) =
                    __floats2half2_rn(acc[mt][nt][2], acc[mt][nt][3]);
            }
        }
    }
    if (vtile) {
        __syncthreads();
        __half* smt = (__half*)smem;     // [NTILE][128]
        #pragma unroll
        for (int mt = 0; mt < 4; mt++) {
            int row0 = wm * 64 + mt * 16 + gid;
            #pragma unroll
            for (int nt = 0; nt < NFRAG; nt++) {
                int col0 = wn * WN + nt * 8 + tig * 2;
                smt[(col0)     * 128 + row0]     = __float2half_rn(acc[mt][nt][0]);
                smt[(col0 + 1) * 128 + row0]     = __float2half_rn(acc[mt][nt][1]);
                smt[(col0)     * 128 + row0 + 8] = __float2half_rn(acc[mt][nt][2]);
                smt[(col0 + 1) * 128 + row0 + 8] = __float2half_rn(acc[mt][nt][3]);
            }
        }
        __syncthreads();
        int b  = by >> 4;
        int s0 = (by & 15) * 128;
        __half* VTb = VTOut + (size_t)b * SS * DD;
        for (int i = tid; i < NTILE * 16; i += 256) {
            int c2 = i >> 4, ch = i & 15;
            int gcol = bx * NTILE + c2;
            if (gcol >= 2 * DD) {
                uint4 v = ((const uint4*)(smt + c2 * 128))[ch];
                *(uint4*)(VTb + (size_t)(gcol - 2 * DD) * SS + s0 + ch * 8) = v;
            }
        }
    }
}

// ===================== SCORES / PV GEMM: 64x64 warp tiles ===================
// 128 thr, 4 warps (2x2 of 64x64), CTA 128x128, 2 CTAs/SM.
// MODE 1: exp2+mask scores, triangular grid, row-partial sums to Rs
// MODE 2: O = inv[row] * (P~ . V^T^T), heavy-first 1D grid
template<int MODE, int LDA, int LDB, int LDC,
         long long SA, long long SB, long long SC>
__global__ void __launch_bounds__(128, 2) mm_w64(
    const __half* __restrict__ Ab, const __half* __restrict__ Bb, void* __restrict__ Cb,
    const float* __restrict__ Rs, float* __restrict__ RsOut, int K)
{
    int bx, by, bz;
    if (MODE == 1) {            // triangular-packed: blockIdx.x -> (bx <= by)
        int t = blockIdx.x;
        by = (int)((sqrtf(8.f * (float)t + 1.f) - 1.f) * 0.5f);
        while ((by + 1) * (by + 2) / 2 <= t) by++;
        while (by * (by + 1) / 2 > t)       by--;
        bx = t - by * (by + 1) / 2;
        bz = blockIdx.z;
    } else {                    // heavy-first 1D
        int i = blockIdx.x;
        by = (SS / 128 - 1) - (i >> 5);
        int inner = i & 31;
        bz = inner >> 3;
        bx = inner & 7;
    }

    extern __shared__ __align__(128) char smem[];
    const uint32_t sb = smem_u32(smem);

    const int tid  = threadIdx.x;
    const int wid  = tid >> 5, lane = tid & 31;
    const int wm   = wid & 1;            // warp row -> 64 rows
    const int wn   = wid >> 1;           // warp col -> 64 cols
    const int gid  = lane >> 2;
    const int tig  = lane & 3;

    const __half* A = Ab + bz * SA + (size_t)by * 128 * LDA;
    const __half* B = Bb + bz * SB + (size_t)bx * 128 * LDB;

    const int kend = (MODE == 2) ? min(K, (by + 1) * 128) : K;
    const int NC   = kend / BK;

    const uint32_t swz    = lane & 7;
    const uint32_t rowA   = wm * 64 + (lane & 15);
    const uint32_t chalfA = lane >> 4;
    const uint32_t rowB   = wn * 64 + (lane & 7) + ((lane >> 4) << 3);
    const uint32_t chalfB = (lane >> 3) & 1;

    auto issue_chunk = [&](int c) {
        const int stg = c - (c / 3) * 3;
        const uint32_t ab = sb + stg * STG_BYTES;
        const uint32_t bb = ab + OPB;
        const int k0 = c * BK;
        #pragma unroll
        for (int i = 0; i < 8; i++) {
            int s = tid + i * 128;
            uint32_t r = s >> 3, f = s & 7;
            uint32_t d = r * 128 + ((f ^ (r & 7)) << 4);
            cp16(ab + d, A + (size_t)r * LDA + k0 + f * 8);
        }
        #pragma unroll
        for (int i = 0; i < 8; i++) {
            int s = tid + i * 128;
            uint32_t r = s >> 3, f = s & 7;
            uint32_t d = r * 128 + ((f ^ (r & 7)) << 4);
            cp16(bb + d, B + (size_t)r * LDB + k0 + f * 8);
        }
        asm volatile("cp.async.commit_group;" ::: "memory");
    };

    float acc[4][8][4];
    #pragma unroll
    for (int i = 0; i < 4; i++)
        #pragma unroll
        for (int j = 0; j < 8; j++)
            #pragma unroll
            for (int t = 0; t < 4; t++) acc[i][j][t] = 0.f;

    issue_chunk(0); issue_chunk(1);

    // MODE 2 prologue: 1/rowsum for this CTA's 128 rows (one per thread)
    if (MODE == 2) {
        const float* rs = Rs + ((size_t)bz * SS + by * 128 + tid) * 16;
        float s = 0.f;
        for (int j = 0; j <= by; j++) s += rs[j];
        ((float*)(smem + INV_OFF))[tid] = 1.0f / s;
    }

    // diagonal score tiles: warp (wm=0, wn=1) output fully masked -> skip math
    const bool dead = (MODE == 1) && (bx == by) && (wm == 0) && (wn == 1);

    for (int c = 0; c < NC; c++) {
        asm volatile("cp.async.wait_group 1;" ::: "memory");
        __syncthreads();
        if (c + 2 < NC) issue_chunk(c + 2);
        else asm volatile("cp.async.commit_group;" ::: "memory");

        const int stg = c - (c / 3) * 3;
        const uint32_t ab = sb + stg * STG_BYTES;
        const uint32_t bb = ab + OPB;

        if (!dead) {
            #pragma unroll
            for (int ks = 0; ks < 4; ks++) {
                uint32_t afr[4][4], bfr[4][4];
                #pragma unroll
                for (int mt = 0; mt < 4; mt++)
                    ldsm_x4(afr[mt][0], afr[mt][1], afr[mt][2], afr[mt][3],
                            ab + (rowA + mt * 16) * 128
                               + ((((ks << 1) | chalfA) ^ swz) << 4));
                #pragma unroll
                for (int nt2 = 0; nt2 < 4; nt2++)
                    ldsm_x4(bfr[nt2][0], bfr[nt2][1], bfr[nt2][2], bfr[nt2][3],
                            bb + (rowB + nt2 * 16) * 128
                               + ((((ks << 1) | chalfB) ^ swz) << 4));
                #pragma unroll
                for (int mt = 0; mt < 4; mt++)
                    #pragma unroll
                    for (int nt = 0; nt < 8; nt++)
                        mma_fp16(acc[mt][nt], afr[mt][0], afr[mt][1], afr[mt][2],
                                 afr[mt][3], bfr[nt >> 1][(nt & 1) * 2],
                                 bfr[nt >> 1][(nt & 1) * 2 + 1]);
            }
        }
    }

    if (MODE == 1) {
        __half* C = (__half*)Cb + bz * SC + (size_t)by * 128 * LDC
                  + (size_t)bx * 128;
        float srow[4][2];
        #pragma unroll
        for (int mt = 0; mt < 4; mt++) { srow[mt][0] = 0.f; srow[mt][1] = 0.f; }

        #pragma unroll
        for (int mt = 0; mt < 4; mt++) {
            int row0 = wm * 64 + mt * 16 + gid;
            int grow0 = by * 128 + row0;        // q
            #pragma unroll
            for (int nt = 0; nt < 8; nt++) {
                int col0 = wn * 64 + nt * 8 + tig * 2;
                int gcol0 = bx * 128 + col0;    // k
                float v0 = (gcol0     <= grow0)     ? exp2f(acc[mt][nt][0] * EXPC) : 0.f;
                float v1 = (gcol0 + 1 <= grow0)     ? exp2f(acc[mt][nt][1] * EXPC) : 0.f;
                float v2 = (gcol0     <= grow0 + 8) ? exp2f(acc[mt][nt][2] * EXPC) : 0.f;
                float v3 = (gcol0 + 1 <= grow0 + 8) ? exp2f(acc[mt][nt][3] * EXPC) : 0.f;
                srow[mt][0] += v0 + v1;
                srow[mt][1] += v2 + v3;
                *(__half2*)(C + (size_t)row0       * LDC + col0) = __floats2half2_rn(v0, v1);
                *(__half2*)(C + (size_t)(row0 + 8) * LDC + col0) = __floats2half2_rn(v2, v3);
            }
        }
        #pragma unroll
        for (int mt = 0; mt < 4; mt++) {
            #pragma unroll
            for (int h = 0; h < 2; h++) {
                float s = srow[mt][h];
                s += __shfl_xor_sync(0xFFFFFFFFu, s, 1);
                s += __shfl_xor_sync(0xFFFFFFFFu, s, 2);
                srow[mt][h] = s;
            }
        }
        __syncthreads();
        float* part = (float*)smem;             // [128][2]
        if (tig == 0) {
            #pragma unroll
            for (int mt = 0; mt < 4; mt++) {
                int rl = wm * 64 + mt * 16 + gid;
                part[rl * 2 + wn]       = srow[mt][0];
                part[(rl + 8) * 2 + wn] = srow[mt][1];
            }
        }
        __syncthreads();
        {
            float s = part[tid * 2] + part[tid * 2 + 1];
            RsOut[((size_t)bz * SS + by * 128 + tid) * 16 + bx] = s;
        }
    } else {
        float* C = (float*)Cb + bz * SC + (size_t)by * 128 * LDC
                 + (size_t)bx * 128;
        const float* invs = (const float*)(smem + INV_OFF);
        #pragma unroll
        for (int mt = 0; mt < 4; mt++) {
            int row0 = wm * 64 + mt * 16 + gid;
            float ia = invs[row0];
            float ib = invs[row0 + 8];
            #pragma unroll
            for (int nt = 0; nt < 8; nt++) {
                int col0 = wn * 64 + nt * 8 + tig * 2;
                *(float2*)(C + (size_t)row0       * LDC + col0) =
                    make_float2(acc[mt][nt][0] * ia, acc[mt][nt][1] * ia);
                *(float2*)(C + (size_t)(row0 + 8) * LDC + col0) =
                    make_float2(acc[mt][nt][2] * ib, acc[mt][nt][3] * ib);
            }
        }
    }
}

// ===================== fused fp32 -> fp16 convert (x | Wq | Wk | Wv) =========
__global__ void __launch_bounds__(256) cvt_all_kernel(
    const float* __restrict__ x,  const float* __restrict__ Wq,
    const float* __restrict__ Wk, const float* __restrict__ Wv,
    __half* __restrict__ X16, __half* __restrict__ Wcat)
{
    int blk = blockIdx.x;
    const float* src;
    __half* dst;
    size_t idx;
    if (blk < 8192) {
        src = x; dst = X16;
        idx = (size_t)blk * 256 + threadIdx.x;
    } else {
        int k = blk - 8192;          // 0..3071
        int w = k >> 10;             // which weight
        src = (w == 0) ? Wq : (w == 1) ? Wk : Wv;
        dst = Wcat + (size_t)w * DD * DD;
        idx = (size_t)(k & 1023) * 256 + threadIdx.x;
    }
    float4 v = ((const float4*)src)[idx];
    ((__half2*)dst)[idx * 2]     = __floats2half2_rn(v.x, v.y);
    ((__half2*)dst)[idx * 2 + 1] = __floats2half2_rn(v.z, v.w);
}

// ===========================================================================
extern "C" void kernel_launch(void* const* d_in, const int* in_sizes, int n_in,
                              void* d_out, int out_size)
{
    const float* x  = (const float*)d_in[0];
    const float* Wq = (const float*)d_in[1];
    const float* Wk = (const float*)d_in[2];
    const float* Wv = (const float*)d_in[3];
    float* out = (float*)d_out;

    __half *X16, *Wcat, *QKV, *VT16, *P16;
    float *rsp;
    cudaGetSymbolAddress((void**)&X16,  g_X16);
    cudaGetSymbolAddress((void**)&Wcat, g_Wcat16);
    cudaGetSymbolAddress((void**)&QKV,  g_QKV16);
    cudaGetSymbolAddress((void**)&VT16, g_VT16);
    cudaGetSymbolAddress((void**)&P16,  g_P16);
    cudaGetSymbolAddress((void**)&rsp,  g_rs);

    constexpr long long sQKV3 = (long long)SS * ND3;
    constexpr long long sV    = (long long)SS * DD;
    constexpr long long sP    = (long long)SS * SS;

    auto kProj  = mm_proj<3, DD, DD, ND3>;
    auto kScore = mm_w64<1, ND3, ND3, SS, sQKV3, sQKV3, sP>;
    auto kOut   = mm_w64<2, SS,  SS,  DD, sP,    sV,    sV>;

    cudaFuncSetAttribute(kProj,  cudaFuncAttributeMaxDynamicSharedMemorySize, SMEM_BYTES);
    cudaFuncSetAttribute(kScore, cudaFuncAttributeMaxDynamicSharedMemorySize, SMEM_BYTES);
    cudaFuncSetAttribute(kOut,   cudaFuncAttributeMaxDynamicSharedMemorySize, SMEM_BYTES);

    // 0) fused fp32 -> fp16 conversion (x + all weights, one launch)
    cvt_all_kernel<<<8192 + 3 * 1024, 256>>>(x, Wq, Wk, Wv, X16, Wcat);

    // 1) Fused QKV projection; V columns written transposed to VT16
    dim3 gProj(ND3 / 96, (BB * SS) / 128, 1);
    kProj<<<gProj, 256, SMEM_BYTES>>>(X16, Wcat, QKV, VT16, DD);

    // 2) Scores + exp + mask + row-partial sums; triangular-packed grid
    const int TTILES = (SS / 128) * (SS / 128 + 1) / 2;   // 136
    dim3 gScore(TTILES, 1, BB);
    kScore<<<gScore, 128, SMEM_BYTES>>>(QKV, QKV + DD, P16, nullptr, rsp, DD);

    // 3) O = diag(1/rowsum) * (P~ @ V); heavy-first 1D grid
    dim3 gOut((DD / 128) * (SS / 128) * BB, 1, 1);
    kOut<<<gOut, 128, SMEM_BYTES>>>(P16, VT16, out, rsp, nullptr, SS);
}